// round 12
// baseline (speedup 1.0000x reference)
#include <cuda_runtime.h>
#include <cuda_fp16.h>
#include <math.h>
#include <stdint.h>

// Problem constants
#define BATCH 2
#define SEQ   2048
#define HID   2048
#define NHQ   16
#define NKV   4
#define HDIM  128
#define ROWS  (BATCH*SEQ)          // 4096
#define QCOLS (NHQ*HDIM)           // 2048
#define KCOLS (NKV*HDIM)           // 512
#define QKVC  (QCOLS + 2*KCOLS)    // 3072

// ---------------------------------------------------------------------------
// Device scratch (static — no allocation allowed)
// A-side operands are fp16 hi-only; B-side operands are fp16 hi+lo.
// ---------------------------------------------------------------------------
__device__ float g_cos[SEQ*64];
__device__ float g_sin[SEQ*64];

__device__ __half g_ah[ROWS*HID];                       // hidden (hi only)
__device__ __half g_ch[ROWS*QCOLS];                     // ctx (hi only)
__device__ __half g_qh[ROWS*QCOLS];                     // q (hi only, rope+scale)
__device__ __half g_kh[ROWS*KCOLS], g_kl[ROWS*KCOLS];   // k hi/lo (rope)
__device__ __half g_vh[ROWS*KCOLS], g_vl[ROWS*KCOLS];   // v hi/lo
__device__ __half g_wh[QKVC*HID],   g_wl[QKVC*HID];     // [Wq;Wk;Wv]^T hi/lo
__device__ __half g_woh[HID*QCOLS], g_wol[HID*QCOLS];   // Wo^T hi/lo

// ---------------------------------------------------------------------------
// Helpers
// ---------------------------------------------------------------------------
__device__ __forceinline__ uint32_t smem_u32(const void* p) {
    uint32_t a;
    asm("{ .reg .u64 t; cvta.to.shared.u64 t, %1; cvt.u32.u64 %0, t; }" : "=r"(a) : "l"(p));
    return a;
}
__device__ __forceinline__ void cp_async16(uint32_t dst, const void* src) {
    asm volatile("cp.async.cg.shared.global [%0], [%1], 16;\n" :: "r"(dst), "l"(src) : "memory");
}
__device__ __forceinline__ void ldsm_x4(uint32_t& r0, uint32_t& r1, uint32_t& r2, uint32_t& r3,
                                        uint32_t addr) {
    asm volatile("ldmatrix.sync.aligned.m8n8.x4.shared.b16 {%0,%1,%2,%3}, [%4];"
                 : "=r"(r0), "=r"(r1), "=r"(r2), "=r"(r3) : "r"(addr));
}
__device__ __forceinline__ void ldsm_x4t(uint32_t& r0, uint32_t& r1, uint32_t& r2, uint32_t& r3,
                                         uint32_t addr) {
    asm volatile("ldmatrix.sync.aligned.m8n8.x4.trans.shared.b16 {%0,%1,%2,%3}, [%4];"
                 : "=r"(r0), "=r"(r1), "=r"(r2), "=r"(r3) : "r"(addr));
}
__device__ __forceinline__ void mma16816(float& c0, float& c1, float& c2, float& c3,
                                         uint32_t a0, uint32_t a1, uint32_t a2, uint32_t a3,
                                         uint32_t b0, uint32_t b1) {
    asm volatile(
        "mma.sync.aligned.m16n8k16.row.col.f32.f16.f16.f32 "
        "{%0,%1,%2,%3}, {%4,%5,%6,%7}, {%8,%9}, {%0,%1,%2,%3};"
        : "+f"(c0), "+f"(c1), "+f"(c2), "+f"(c3)
        : "r"(a0), "r"(a1), "r"(a2), "r"(a3), "r"(b0), "r"(b1));
}
// flash smem swizzle: row r (256B rows of fp16[128]), 16B chunk c (0..15)
#define SW(r, c) ((uint32_t)((r) * 256 + (((c) ^ ((r) & 7)) << 4)))
// gemm smem swizzle: row r (128B rows of fp16[64]), 16B chunk c (0..7)
#define SWG(r, c) ((uint32_t)((r) * 128 + (((c) ^ ((r) & 7)) << 4)))

// ---------------------------------------------------------------------------
// fp32 -> fp16 hi (row-major, same layout)
// ---------------------------------------------------------------------------
__global__ void split_hi_kernel(const float* __restrict__ in,
                                __half* __restrict__ hi, int n4)
{
    int i = blockIdx.x * blockDim.x + threadIdx.x;
    if (i >= n4) return;
    float4 v = reinterpret_cast<const float4*>(in)[i];
    __half2* hp = reinterpret_cast<__half2*>(hi);
    hp[2*i]   = __floats2half2_rn(v.x, v.y);
    hp[2*i+1] = __floats2half2_rn(v.z, v.w);
}

// All four weight transposes+splits (fp16 hi/lo) in ONE launch.
__global__ void tsplit_all_kernel(const float* __restrict__ Wq, const float* __restrict__ Wk,
                                  const float* __restrict__ Wv, const float* __restrict__ Wo,
                                  __half* __restrict__ wh, __half* __restrict__ wl,
                                  __half* __restrict__ woh, __half* __restrict__ wol)
{
    __shared__ float t[32][33];
    const int bid = blockIdx.x;
    const float* src;
    __half *dh, *dl;
    int Nin, nbx, tile;
    if (bid < 4096)      { src = Wq; dh = wh; dl = wl; Nin = 2048; nbx = 64; tile = bid; }
    else if (bid < 5120) { src = Wk; dh = wh + (size_t)QCOLS*HID; dl = wl + (size_t)QCOLS*HID;
                           Nin = 512; nbx = 16; tile = bid - 4096; }
    else if (bid < 6144) { src = Wv; dh = wh + (size_t)(QCOLS+KCOLS)*HID; dl = wl + (size_t)(QCOLS+KCOLS)*HID;
                           Nin = 512; nbx = 16; tile = bid - 5120; }
    else                 { src = Wo; dh = woh; dl = wol; Nin = 2048; nbx = 64; tile = bid - 6144; }

    const int tx = threadIdx.x, ty = threadIdx.y;
    const int n0 = (tile % nbx) * 32, k0 = (tile / nbx) * 32;
    #pragma unroll
    for (int j = 0; j < 32; j += 8)
        t[ty + j][tx] = src[(size_t)(k0 + ty + j) * Nin + n0 + tx];
    __syncthreads();
    #pragma unroll
    for (int j = 0; j < 32; j += 8) {
        float x = t[tx][ty + j];
        __half h = __float2half_rn(x);
        __half l = __float2half_rn(x - __half2float(h));
        size_t o = (size_t)(n0 + ty + j) * 2048 + k0 + tx;
        dh[o] = h;
        dl[o] = l;
    }
}

// ---------------------------------------------------------------------------
// RoPE table
// ---------------------------------------------------------------------------
__global__ void rope_table_kernel()
{
    int idx = blockIdx.x * blockDim.x + threadIdx.x;
    if (idx >= SEQ * 64) return;
    int pos = idx >> 6, i = idx & 63;
    double inv = exp2(-(double)i * (13.287712379549449 / 64.0));
    double ang = (double)pos * inv;
    const double twopi = 6.283185307179586476925286766559;
    ang -= floor(ang * (1.0 / twopi)) * twopi;
    if (ang > 3.14159265358979323846) ang -= twopi;
    float s, c;
    sincosf((float)ang, &s, &c);
    g_cos[idx] = c;
    g_sin[idx] = s;
}

// ---------------------------------------------------------------------------
// GEMM mainloop: 128x128 CTA tile, fp16 2-product (Ah*Bh + Ah*Bl).
// KCH=64 (32 chunks), 2-stage double buffer, one sync per chunk, 2 CTAs/SM.
// Stage layout: [Ah 16KB][Bh 16KB][Bl 16KB] = 48KB; 2 stages = 96KB.
// ---------------------------------------------------------------------------
#define KCH       64
#define NCHUNKS   32
#define TILE_B    16384           // 128 rows x 128 B
#define STAGE_B   (3*TILE_B)      // 48 KB
#define NSTG      2
#define GEMM_SMEM (NSTG*STAGE_B)  // 96 KB

struct GemmCtx {
    uint32_t sbase;
    const __half* gsrc;   // null => this thread group loads nothing
    int row0, lch, lr0;
    uint32_t smoff;
    int m0w, n0w;
    int a_row, a_kh, b_row, b_kh;
};

__device__ __forceinline__ void gemm_mainloop(
    const GemmCtx& cx, float acc[4][4][4])
{
    auto load_chunk = [&](int ci, int st) {
        if (cx.gsrc) {
            const uint32_t tb = cx.sbase + st * STAGE_B + cx.smoff;
            #pragma unroll
            for (int i = 0; i < 16; i++) {
                const int r = cx.lr0 + i * 8;
                const uint32_t dst = tb + SWG(r, cx.lch);
                cp_async16(dst, cx.gsrc + (size_t)(cx.row0 + r) * 2048 + ci * KCH + cx.lch * 8);
            }
        }
        asm volatile("cp.async.commit_group;\n" ::: "memory");
    };

    load_chunk(0, 0);

    for (int ci = 0; ci < NCHUNKS; ci++) {
        asm volatile("cp.async.wait_group 0;\n" ::: "memory");
        __syncthreads();
        if (ci + 1 < NCHUNKS) load_chunk(ci + 1, (ci + 1) & 1);

        const uint32_t ah_b = cx.sbase + (ci & 1) * STAGE_B;
        const uint32_t bh_b = ah_b + TILE_B;
        const uint32_t bl_b = ah_b + 2 * TILE_B;

        #pragma unroll
        for (int ks = 0; ks < 4; ks++) {
            uint32_t a4[4][4];
            #pragma unroll
            for (int mi = 0; mi < 4; mi++) {
                const int r = cx.m0w + mi * 16 + cx.a_row;
                ldsm_x4(a4[mi][0], a4[mi][1], a4[mi][2], a4[mi][3],
                        ah_b + SWG(r, ks * 2 + cx.a_kh));
            }
            uint32_t bh[4][2], bl[4][2];
            #pragma unroll
            for (int jb = 0; jb < 2; jb++) {
                const int r = cx.n0w + jb * 16 + cx.b_row;
                const uint32_t off = SWG(r, ks * 2 + cx.b_kh);
                ldsm_x4(bh[2*jb][0], bh[2*jb][1], bh[2*jb+1][0], bh[2*jb+1][1], bh_b + off);
                ldsm_x4(bl[2*jb][0], bl[2*jb][1], bl[2*jb+1][0], bl[2*jb+1][1], bl_b + off);
            }
            // Pass 1: Ah*Bh (16 independent accumulators)
            #pragma unroll
            for (int mi = 0; mi < 4; mi++)
                #pragma unroll
                for (int nj = 0; nj < 4; nj++) {
                    float* cc = acc[mi][nj];
                    mma16816(cc[0], cc[1], cc[2], cc[3],
                             a4[mi][0], a4[mi][1], a4[mi][2], a4[mi][3],
                             bh[nj][0], bh[nj][1]);
                }
            // Pass 2: Ah*Bl
            #pragma unroll
            for (int mi = 0; mi < 4; mi++)
                #pragma unroll
                for (int nj = 0; nj < 4; nj++) {
                    float* cc = acc[mi][nj];
                    mma16816(cc[0], cc[1], cc[2], cc[3],
                             a4[mi][0], a4[mi][1], a4[mi][2], a4[mi][3],
                             bl[nj][0], bl[nj][1]);
                }
        }
    }
}

__device__ __forceinline__ void gemm_init_ctx(
    GemmCtx& cx, uint32_t sbase, int tid, int m0, int n0,
    const __half* Ah, const __half* Bh, const __half* Bl)
{
    cx.sbase = sbase;
    const int tt = tid >> 6;
    const int t6 = tid & 63;
    cx.lch = t6 & 7;
    cx.lr0 = t6 >> 3;
    switch (tt) {
        case 0:  cx.gsrc = Ah; cx.row0 = m0; cx.smoff = 0;          break;
        case 1:  cx.gsrc = Bh; cx.row0 = n0; cx.smoff = TILE_B;     break;
        case 2:  cx.gsrc = Bl; cx.row0 = n0; cx.smoff = 2*TILE_B;   break;
        default: cx.gsrc = nullptr; cx.row0 = 0; cx.smoff = 0;      break;
    }
    const int wid = tid >> 5, lane = tid & 31;
    cx.m0w = (wid & 1) * 64;
    cx.n0w = (wid >> 1) * 32;
    cx.a_row = lane & 15;
    cx.a_kh  = lane >> 4;
    cx.b_row = (lane & 7) + ((lane >> 4) & 1) * 8;
    cx.b_kh  = (lane >> 3) & 1;
}

// ---------------------------------------------------------------------------
// Plain GEMM (fp32 C output) — output projection.
// ---------------------------------------------------------------------------
__global__ __launch_bounds__(256, 2)
void gemm_mma(const __half* __restrict__ Ah,
              const __half* __restrict__ Bh, const __half* __restrict__ Bl,
              float* __restrict__ C, int ldc)
{
    extern __shared__ char dsm[];
    const int tid = threadIdx.x;
    const int lane = tid & 31;
    const int m0 = blockIdx.y * 128;
    const int n0 = blockIdx.x * 128;

    GemmCtx cx;
    gemm_init_ctx(cx, smem_u32(dsm), tid, m0, n0, Ah, Bh, Bl);

    float acc[4][4][4];
    #pragma unroll
    for (int i = 0; i < 4; i++)
        #pragma unroll
        for (int j = 0; j < 4; j++)
            #pragma unroll
            for (int q = 0; q < 4; q++) acc[i][j][q] = 0.0f;

    gemm_mainloop(cx, acc);

    const int er = lane >> 2;
    const int ec = (lane & 3) * 2;
    #pragma unroll
    for (int mi = 0; mi < 4; mi++) {
        const int row_a = m0 + cx.m0w + mi * 16 + er;
        #pragma unroll
        for (int nj = 0; nj < 4; nj++) {
            const int col = n0 + cx.n0w + nj * 8 + ec;
            float* cc = acc[mi][nj];
            *reinterpret_cast<float2*>(C + (size_t)row_a * ldc + col) =
                make_float2(cc[0], cc[1]);
            *reinterpret_cast<float2*>(C + (size_t)(row_a + 8) * ldc + col) =
                make_float2(cc[2], cc[3]);
        }
    }
}

// ---------------------------------------------------------------------------
// QKV GEMM with fused RoPE + scale + fp16 split epilogue.
// ---------------------------------------------------------------------------
__global__ __launch_bounds__(256, 2)
void gemm_qkv_fused(const __half* __restrict__ Ah,
                    const __half* __restrict__ Bh, const __half* __restrict__ Bl,
                    __half* __restrict__ Qh,
                    __half* __restrict__ Kh, __half* __restrict__ Kl,
                    __half* __restrict__ Vh, __half* __restrict__ Vl)
{
    extern __shared__ char dsm[];
    const int tid = threadIdx.x;
    const int lane = tid & 31;
    const int m0 = blockIdx.y * 128;
    const int n0 = blockIdx.x * 128;

    GemmCtx cx;
    gemm_init_ctx(cx, smem_u32(dsm), tid, m0, n0, Ah, Bh, Bl);

    float acc[4][4][4];
    #pragma unroll
    for (int i = 0; i < 4; i++)
        #pragma unroll
        for (int j = 0; j < 4; j++)
            #pragma unroll
            for (int q = 0; q < 4; q++) acc[i][j][q] = 0.0f;

    gemm_mainloop(cx, acc);

    // ---- stage fp32 tile to smem [128][132] (67.6KB <= 96KB) ----
    __syncthreads();
    float* ft = reinterpret_cast<float*>(dsm);
    const int er = lane >> 2;
    const int ec = (lane & 3) * 2;
    #pragma unroll
    for (int mi = 0; mi < 4; mi++) {
        const int r = cx.m0w + mi * 16 + er;
        #pragma unroll
        for (int nj = 0; nj < 4; nj++) {
            const int c = cx.n0w + nj * 8 + ec;
            float* cc = acc[mi][nj];
            *reinterpret_cast<float2*>(ft + r * 132 + c)       = make_float2(cc[0], cc[1]);
            *reinterpret_cast<float2*>(ft + (r + 8) * 132 + c) = make_float2(cc[2], cc[3]);
        }
    }
    __syncthreads();

    // ---- fused epilogue by region ----
    if (n0 < QCOLS) {
        const int head = n0 >> 7;
        const float scale = 0.08838834764831845f;
        for (int it = 0; it < 32; it++) {
            const int idx = tid + it * 256;
            const int r = idx >> 6, i = idx & 63;
            const int grow = m0 + r;
            const int pos = grow & (SEQ - 1);
            const float x1 = ft[r * 132 + i];
            const float x2 = ft[r * 132 + i + 64];
            const float c = g_cos[pos * 64 + i];
            const float s = g_sin[pos * 64 + i];
            const float y1 = (x1 * c - x2 * s) * scale;
            const float y2 = (x2 * c + x1 * s) * scale;
            const size_t o = (size_t)grow * QCOLS + head * HDIM + i;
            Qh[o]      = __float2half_rn(y1);
            Qh[o + 64] = __float2half_rn(y2);
        }
    } else if (n0 < QCOLS + KCOLS) {
        const int head = (n0 - QCOLS) >> 7;
        for (int it = 0; it < 32; it++) {
            const int idx = tid + it * 256;
            const int r = idx >> 6, i = idx & 63;
            const int grow = m0 + r;
            const int pos = grow & (SEQ - 1);
            const float x1 = ft[r * 132 + i];
            const float x2 = ft[r * 132 + i + 64];
            const float c = g_cos[pos * 64 + i];
            const float s = g_sin[pos * 64 + i];
            const float y1 = x1 * c - x2 * s;
            const float y2 = x2 * c + x1 * s;
            const __half h1 = __float2half_rn(y1);
            const __half h2 = __float2half_rn(y2);
            const size_t o = (size_t)grow * KCOLS + head * HDIM + i;
            Kh[o]      = h1;
            Kh[o + 64] = h2;
            Kl[o]      = __float2half_rn(y1 - __half2float(h1));
            Kl[o + 64] = __float2half_rn(y2 - __half2float(h2));
        }
    } else {
        const int cbase = n0 - (QCOLS + KCOLS);
        for (int it = 0; it < 64; it++) {
            const int idx = tid + it * 256;
            const int r = idx >> 7, c = idx & 127;
            const int grow = m0 + r;
            const float x = ft[r * 132 + c];
            const __half h = __float2half_rn(x);
            const size_t o = (size_t)grow * KCOLS + cbase + c;
            Vh[o] = h;
            Vl[o] = __float2half_rn(x - __half2float(h));
        }
    }
}

// ---------------------------------------------------------------------------
// Flash attention, fp16 2-product. SINGLE-stage KV buffer -> 96KB smem ->
// 2 CTAs/SM; cross-CTA overlap hides loads and softmax phases.
// qt processed descending (heavy tiles first). Writes ctx hi only.
// ---------------------------------------------------------------------------
#define FQT 128
#define FKT 64
#define FQ_B    32768
#define FTILE_B 16384
#define FKV_B   (4*FTILE_B)                 // Kh,Kl,Vh,Vl (one stage)
#define FLASH_SMEM (FQ_B + FKV_B)           // 96KB

__global__ __launch_bounds__(256, 2)
void flash_mma(const __half* __restrict__ Qh_g,
               const __half* __restrict__ Kh_g, const __half* __restrict__ Kl_g,
               const __half* __restrict__ Vh_g, const __half* __restrict__ Vl_g,
               __half* __restrict__ Ch_g)
{
    extern __shared__ char dsm[];
    const uint32_t sb = smem_u32(dsm);
    const uint32_t Qh_s = sb;
    const uint32_t KV_s = sb + FQ_B;

    const int tid = threadIdx.x;
    const int w = tid >> 5, lane = tid & 31;
    const int qt = gridDim.x - 1 - blockIdx.x;
    const int h = blockIdx.y, b = blockIdx.z;
    const int kvh = h >> 2;
    const int qrow0 = b * SEQ + qt * FQT;
    const int nkt = 2 * qt + 2;

    {
        const int c = tid & 15, r0 = tid >> 4;
        #pragma unroll
        for (int i = 0; i < 8; i++) {
            const int r = r0 + i * 16;
            const size_t go = (size_t)(qrow0 + r) * QCOLS + h * HDIM + c * 8;
            cp_async16(Qh_s + SW(r, c), Qh_g + go);
        }
    }

    auto load_kv = [&](int kt) {
        const int c = tid & 15, r0 = tid >> 4;
        const int krow0 = b * SEQ + kt * FKT;
        #pragma unroll
        for (int i = 0; i < 4; i++) {
            const int r = r0 + i * 16;
            const size_t go = (size_t)(krow0 + r) * KCOLS + kvh * HDIM + c * 8;
            cp_async16(KV_s +             SW(r, c), Kh_g + go);
            cp_async16(KV_s +   FTILE_B + SW(r, c), Kl_g + go);
            cp_async16(KV_s + 2*FTILE_B + SW(r, c), Vh_g + go);
            cp_async16(KV_s + 3*FTILE_B + SW(r, c), Vl_g + go);
        }
        asm volatile("cp.async.commit_group;\n" ::: "memory");
    };

    load_kv(0);   // group 0 also carries the Q loads

    const int er = lane >> 2, ec = lane & 3;
    const int a_row = w * 16 + (lane & 15);
    const int a_kh  = lane >> 4;
    const int b_n   = (lane & 7) + ((lane >> 4) & 1) * 8;
    const int b_kh  = (lane >> 3) & 1;
    const int v_key = (lane & 7) + ((lane >> 3) & 1) * 8;
    const int v_dc  = lane >> 4;

    const int rg0 = qt * FQT + w * 16 + er;
    const int rg1 = rg0 + 8;

    float o[16][4];
    #pragma unroll
    for (int j = 0; j < 16; j++)
        #pragma unroll
        for (int q = 0; q < 4; q++) o[j][q] = 0.0f;
    float m0 = -1e30f, m1 = -1e30f, l0 = 0.0f, l1 = 0.0f;

    const uint32_t Kh_s = KV_s;
    const uint32_t Kl_s = KV_s + FTILE_B;
    const uint32_t Vh_s = KV_s + 2 * FTILE_B;
    const uint32_t Vl_s = KV_s + 3 * FTILE_B;

    for (int kt = 0; kt < nkt; kt++) {
        asm volatile("cp.async.wait_group 0;\n" ::: "memory");
        __syncthreads();

        float s[8][4];
        #pragma unroll
        for (int f = 0; f < 8; f++)
            #pragma unroll
            for (int q = 0; q < 4; q++) s[f][q] = 0.0f;

        #pragma unroll
        for (int ks = 0; ks < 8; ks++) {
            uint32_t qa[4];
            ldsm_x4(qa[0], qa[1], qa[2], qa[3], Qh_s + SW(a_row, ks*2 + a_kh));
            #pragma unroll
            for (int ng = 0; ng < 4; ng++) {
                uint32_t kh0, kh1, kh2, kh3, kl0, kl1, kl2, kl3;
                ldsm_x4(kh0, kh1, kh2, kh3, Kh_s + SW(ng*16 + b_n, ks*2 + b_kh));
                ldsm_x4(kl0, kl1, kl2, kl3, Kl_s + SW(ng*16 + b_n, ks*2 + b_kh));
                float* s0 = s[ng*2];
                float* s1 = s[ng*2 + 1];
                mma16816(s0[0], s0[1], s0[2], s0[3], qa[0], qa[1], qa[2], qa[3], kh0, kh1);
                mma16816(s1[0], s1[1], s1[2], s1[3], qa[0], qa[1], qa[2], qa[3], kh2, kh3);
                mma16816(s0[0], s0[1], s0[2], s0[3], qa[0], qa[1], qa[2], qa[3], kl0, kl1);
                mma16816(s1[0], s1[1], s1[2], s1[3], qa[0], qa[1], qa[2], qa[3], kl2, kl3);
            }
        }

        if (kt >= 2 * qt) {
            #pragma unroll
            for (int f = 0; f < 8; f++) {
                const int key0 = kt * FKT + f * 8 + ec * 2;
                if (key0     > rg0) s[f][0] = -1e30f;
                if (key0 + 1 > rg0) s[f][1] = -1e30f;
                if (key0     > rg1) s[f][2] = -1e30f;
                if (key0 + 1 > rg1) s[f][3] = -1e30f;
            }
        }

        float nm0 = -1e30f, nm1 = -1e30f;
        #pragma unroll
        for (int f = 0; f < 8; f++) {
            nm0 = fmaxf(nm0, fmaxf(s[f][0], s[f][1]));
            nm1 = fmaxf(nm1, fmaxf(s[f][2], s[f][3]));
        }
        nm0 = fmaxf(nm0, __shfl_xor_sync(0xffffffffu, nm0, 1));
        nm0 = fmaxf(nm0, __shfl_xor_sync(0xffffffffu, nm0, 2));
        nm1 = fmaxf(nm1, __shfl_xor_sync(0xffffffffu, nm1, 1));
        nm1 = fmaxf(nm1, __shfl_xor_sync(0xffffffffu, nm1, 2));
        nm0 = fmaxf(nm0, m0);
        nm1 = fmaxf(nm1, m1);
        const float corr0 = __expf(m0 - nm0);
        const float corr1 = __expf(m1 - nm1);
        m0 = nm0;
        m1 = nm1;

        float rs0 = 0.0f, rs1 = 0.0f;
        #pragma unroll
        for (int f = 0; f < 8; f++) {
            s[f][0] = __expf(s[f][0] - nm0);
            s[f][1] = __expf(s[f][1] - nm0);
            s[f][2] = __expf(s[f][2] - nm1);
            s[f][3] = __expf(s[f][3] - nm1);
            rs0 += s[f][0] + s[f][1];
            rs1 += s[f][2] + s[f][3];
        }
        rs0 += __shfl_xor_sync(0xffffffffu, rs0, 1);
        rs0 += __shfl_xor_sync(0xffffffffu, rs0, 2);
        rs1 += __shfl_xor_sync(0xffffffffu, rs1, 1);
        rs1 += __shfl_xor_sync(0xffffffffu, rs1, 2);
        l0 = l0 * corr0 + rs0;
        l1 = l1 * corr1 + rs1;
        #pragma unroll
        for (int j = 0; j < 16; j++) {
            o[j][0] *= corr0; o[j][1] *= corr0;
            o[j][2] *= corr1; o[j][3] *= corr1;
        }

        #pragma unroll
        for (int kp = 0; kp < 4; kp++) {
            const float* f0 = s[2*kp];
            const float* f1 = s[2*kp + 1];
            uint32_t pa[4];
            __half2 t;
            t = __floats2half2_rn(f0[0], f0[1]); pa[0] = *reinterpret_cast<uint32_t*>(&t);
            t = __floats2half2_rn(f0[2], f0[3]); pa[1] = *reinterpret_cast<uint32_t*>(&t);
            t = __floats2half2_rn(f1[0], f1[1]); pa[2] = *reinterpret_cast<uint32_t*>(&t);
            t = __floats2half2_rn(f1[2], f1[3]); pa[3] = *reinterpret_cast<uint32_t*>(&t);

            #pragma unroll
            for (int nd = 0; nd < 8; nd++) {
                uint32_t vh0, vh1, vh2, vh3, vl0, vl1, vl2, vl3;
                ldsm_x4t(vh0, vh1, vh2, vh3, Vh_s + SW(kp*16 + v_key, nd*2 + v_dc));
                ldsm_x4t(vl0, vl1, vl2, vl3, Vl_s + SW(kp*16 + v_key, nd*2 + v_dc));
                float* o0 = o[nd*2];
                float* o1 = o[nd*2 + 1];
                mma16816(o0[0], o0[1], o0[2], o0[3], pa[0], pa[1], pa[2], pa[3], vh0, vh1);
                mma16816(o1[0], o1[1], o1[2], o1[3], pa[0], pa[1], pa[2], pa[3], vh2, vh3);
                mma16816(o0[0], o0[1], o0[2], o0[3], pa[0], pa[1], pa[2], pa[3], vl0, vl1);
                mma16816(o1[0], o1[1], o1[2], o1[3], pa[0], pa[1], pa[2], pa[3], vl2, vl3);
            }
        }

        // all reads of the KV stage are done — safe to overwrite
        __syncthreads();
        if (kt + 1 < nkt) load_kv(kt + 1);
    }

    const float inv0 = 1.0f / l0;
    const float inv1 = 1.0f / l1;
    const size_t row0 = (size_t)(qrow0 + w * 16 + er);
    const size_t row1 = row0 + 8;
    #pragma unroll
    for (int j = 0; j < 16; j++) {
        const int col = h * HDIM + j * 8 + ec * 2;
        *reinterpret_cast<__half2*>(Ch_g + row0 * QCOLS + col) =
            __floats2half2_rn(o[j][0] * inv0, o[j][1] * inv0);
        *reinterpret_cast<__half2*>(Ch_g + row1 * QCOLS + col) =
            __floats2half2_rn(o[j][2] * inv1, o[j][3] * inv1);
    }
}

// ---------------------------------------------------------------------------
extern "C" void kernel_launch(void* const* d_in, const int* in_sizes, int n_in,
                              void* d_out, int out_size)
{
    const float* hidden = (const float*)d_in[0];
    const float* Wq = (const float*)d_in[1];
    const float* Wk = (const float*)d_in[2];
    const float* Wv = (const float*)d_in[3];
    const float* Wo = (const float*)d_in[4];
    float* out = (float*)d_out;

    __half *ah, *ch, *qh, *kh, *kl, *vh, *vl, *wh, *wl, *woh, *wol;
    cudaGetSymbolAddress((void**)&ah, g_ah);
    cudaGetSymbolAddress((void**)&ch, g_ch);
    cudaGetSymbolAddress((void**)&qh, g_qh);
    cudaGetSymbolAddress((void**)&kh, g_kh);  cudaGetSymbolAddress((void**)&kl, g_kl);
    cudaGetSymbolAddress((void**)&vh, g_vh);  cudaGetSymbolAddress((void**)&vl, g_vl);
    cudaGetSymbolAddress((void**)&wh, g_wh);  cudaGetSymbolAddress((void**)&wl, g_wl);
    cudaGetSymbolAddress((void**)&woh, g_woh); cudaGetSymbolAddress((void**)&wol, g_wol);

    cudaFuncSetAttribute(gemm_mma,
                         cudaFuncAttributeMaxDynamicSharedMemorySize, GEMM_SMEM);
    cudaFuncSetAttribute(gemm_qkv_fused,
                         cudaFuncAttributeMaxDynamicSharedMemorySize, GEMM_SMEM);
    cudaFuncSetAttribute(flash_mma,
                         cudaFuncAttributeMaxDynamicSharedMemorySize, FLASH_SMEM);

    // 1) RoPE table, 2) hidden hi-split, 3) all weight transposes (one launch)
    rope_table_kernel<<<(SEQ*64 + 255)/256, 256>>>();
    split_hi_kernel<<<(ROWS*HID/4 + 255)/256, 256>>>(hidden, ah, ROWS*HID/4);
    tsplit_all_kernel<<<10240, dim3(32,8)>>>(Wq, Wk, Wv, Wo, wh, wl, woh, wol);

    // 4) Merged QKV projection with fused RoPE/scale/split epilogue
    gemm_qkv_fused<<<dim3(QKVC/128, ROWS/128), 256, GEMM_SMEM>>>(
        ah, wh, wl, qh, kh, kl, vh, vl);

    // 5) Attention, writes ctx hi directly
    flash_mma<<<dim3(SEQ/FQT, NHQ, BATCH), 256, FLASH_SMEM>>>(qh, kh, kl, vh, vl, ch);

    // 6) Output projection
    gemm_mma<<<dim3(HID/128, ROWS/128), 256, GEMM_SMEM>>>(ch, woh, wol, out, HID);
}

// round 13
// speedup vs baseline: 1.0044x; 1.0044x over previous
#include <cuda_runtime.h>
#include <cuda_fp16.h>
#include <math.h>
#include <stdint.h>

// Problem constants
#define BATCH 2
#define SEQ   2048
#define HID   2048
#define NHQ   16
#define NKV   4
#define HDIM  128
#define ROWS  (BATCH*SEQ)          // 4096
#define QCOLS (NHQ*HDIM)           // 2048
#define KCOLS (NKV*HDIM)           // 512
#define QKVC  (QCOLS + 2*KCOLS)    // 3072

// ---------------------------------------------------------------------------
// Device scratch (static — no allocation allowed)
// A-side operands are fp16 hi-only; B-side operands are fp16 hi+lo.
// ---------------------------------------------------------------------------
__device__ float g_cos[SEQ*64];
__device__ float g_sin[SEQ*64];

__device__ __half g_ah[ROWS*HID];                       // hidden (hi only)
__device__ __half g_ch[ROWS*QCOLS];                     // ctx (hi only)
__device__ __half g_qh[ROWS*QCOLS];                     // q (hi only, rope+scale)
__device__ __half g_kh[ROWS*KCOLS], g_kl[ROWS*KCOLS];   // k hi/lo (rope)
__device__ __half g_vh[ROWS*KCOLS], g_vl[ROWS*KCOLS];   // v hi/lo
__device__ __half g_wh[QKVC*HID],   g_wl[QKVC*HID];     // [Wq;Wk;Wv]^T hi/lo
__device__ __half g_woh[HID*QCOLS], g_wol[HID*QCOLS];   // Wo^T hi/lo

// ---------------------------------------------------------------------------
// Helpers
// ---------------------------------------------------------------------------
__device__ __forceinline__ uint32_t smem_u32(const void* p) {
    uint32_t a;
    asm("{ .reg .u64 t; cvta.to.shared.u64 t, %1; cvt.u32.u64 %0, t; }" : "=r"(a) : "l"(p));
    return a;
}
__device__ __forceinline__ void cp_async16(uint32_t dst, const void* src) {
    asm volatile("cp.async.cg.shared.global [%0], [%1], 16;\n" :: "r"(dst), "l"(src) : "memory");
}
__device__ __forceinline__ void ldsm_x4(uint32_t& r0, uint32_t& r1, uint32_t& r2, uint32_t& r3,
                                        uint32_t addr) {
    asm volatile("ldmatrix.sync.aligned.m8n8.x4.shared.b16 {%0,%1,%2,%3}, [%4];"
                 : "=r"(r0), "=r"(r1), "=r"(r2), "=r"(r3) : "r"(addr));
}
__device__ __forceinline__ void ldsm_x4t(uint32_t& r0, uint32_t& r1, uint32_t& r2, uint32_t& r3,
                                         uint32_t addr) {
    asm volatile("ldmatrix.sync.aligned.m8n8.x4.trans.shared.b16 {%0,%1,%2,%3}, [%4];"
                 : "=r"(r0), "=r"(r1), "=r"(r2), "=r"(r3) : "r"(addr));
}
__device__ __forceinline__ void mma16816(float& c0, float& c1, float& c2, float& c3,
                                         uint32_t a0, uint32_t a1, uint32_t a2, uint32_t a3,
                                         uint32_t b0, uint32_t b1) {
    asm volatile(
        "mma.sync.aligned.m16n8k16.row.col.f32.f16.f16.f32 "
        "{%0,%1,%2,%3}, {%4,%5,%6,%7}, {%8,%9}, {%0,%1,%2,%3};"
        : "+f"(c0), "+f"(c1), "+f"(c2), "+f"(c3)
        : "r"(a0), "r"(a1), "r"(a2), "r"(a3), "r"(b0), "r"(b1));
}
// flash smem swizzle: row r (256B rows of fp16[128]), 16B chunk c (0..15)
#define SW(r, c) ((uint32_t)((r) * 256 + (((c) ^ ((r) & 7)) << 4)))
// gemm smem swizzle: row r (128B rows of fp16[64]), 16B chunk c (0..7)
#define SWG(r, c) ((uint32_t)((r) * 128 + (((c) ^ ((r) & 7)) << 4)))

// ---------------------------------------------------------------------------
// fp32 -> fp16 hi (row-major, same layout)
// ---------------------------------------------------------------------------
__global__ void split_hi_kernel(const float* __restrict__ in,
                                __half* __restrict__ hi, int n4)
{
    int i = blockIdx.x * blockDim.x + threadIdx.x;
    if (i >= n4) return;
    float4 v = reinterpret_cast<const float4*>(in)[i];
    __half2* hp = reinterpret_cast<__half2*>(hi);
    hp[2*i]   = __floats2half2_rn(v.x, v.y);
    hp[2*i+1] = __floats2half2_rn(v.z, v.w);
}

// All four weight transposes+splits (fp16 hi/lo) in ONE launch.
__global__ void tsplit_all_kernel(const float* __restrict__ Wq, const float* __restrict__ Wk,
                                  const float* __restrict__ Wv, const float* __restrict__ Wo,
                                  __half* __restrict__ wh, __half* __restrict__ wl,
                                  __half* __restrict__ woh, __half* __restrict__ wol)
{
    __shared__ float t[32][33];
    const int bid = blockIdx.x;
    const float* src;
    __half *dh, *dl;
    int Nin, nbx, tile;
    if (bid < 4096)      { src = Wq; dh = wh; dl = wl; Nin = 2048; nbx = 64; tile = bid; }
    else if (bid < 5120) { src = Wk; dh = wh + (size_t)QCOLS*HID; dl = wl + (size_t)QCOLS*HID;
                           Nin = 512; nbx = 16; tile = bid - 4096; }
    else if (bid < 6144) { src = Wv; dh = wh + (size_t)(QCOLS+KCOLS)*HID; dl = wl + (size_t)(QCOLS+KCOLS)*HID;
                           Nin = 512; nbx = 16; tile = bid - 5120; }
    else                 { src = Wo; dh = woh; dl = wol; Nin = 2048; nbx = 64; tile = bid - 6144; }

    const int tx = threadIdx.x, ty = threadIdx.y;
    const int n0 = (tile % nbx) * 32, k0 = (tile / nbx) * 32;
    #pragma unroll
    for (int j = 0; j < 32; j += 8)
        t[ty + j][tx] = src[(size_t)(k0 + ty + j) * Nin + n0 + tx];
    __syncthreads();
    #pragma unroll
    for (int j = 0; j < 32; j += 8) {
        float x = t[tx][ty + j];
        __half h = __float2half_rn(x);
        __half l = __float2half_rn(x - __half2float(h));
        size_t o = (size_t)(n0 + ty + j) * 2048 + k0 + tx;
        dh[o] = h;
        dl[o] = l;
    }
}

// ---------------------------------------------------------------------------
// RoPE table
// ---------------------------------------------------------------------------
__global__ void rope_table_kernel()
{
    int idx = blockIdx.x * blockDim.x + threadIdx.x;
    if (idx >= SEQ * 64) return;
    int pos = idx >> 6, i = idx & 63;
    double inv = exp2(-(double)i * (13.287712379549449 / 64.0));
    double ang = (double)pos * inv;
    const double twopi = 6.283185307179586476925286766559;
    ang -= floor(ang * (1.0 / twopi)) * twopi;
    if (ang > 3.14159265358979323846) ang -= twopi;
    float s, c;
    sincosf((float)ang, &s, &c);
    g_cos[idx] = c;
    g_sin[idx] = s;
}

// ---------------------------------------------------------------------------
// GEMM mainloop: 128x128 CTA tile, fp16 2-product (Ah*Bh + Ah*Bl).
// KCH=64 (32 chunks), 2-stage double buffer, one sync per chunk, 2 CTAs/SM.
// Stage layout: [Ah 16KB][Bh 16KB][Bl 16KB] = 48KB; 2 stages = 96KB.
// ---------------------------------------------------------------------------
#define KCH       64
#define NCHUNKS   32
#define TILE_B    16384           // 128 rows x 128 B
#define STAGE_B   (3*TILE_B)      // 48 KB
#define NSTG      2
#define GEMM_SMEM (NSTG*STAGE_B)  // 96 KB

struct GemmCtx {
    uint32_t sbase;
    const __half* gsrc;   // null => this thread group loads nothing
    int row0, lch, lr0;
    uint32_t smoff;
    int m0w, n0w;
    int a_row, a_kh, b_row, b_kh;
};

__device__ __forceinline__ void gemm_mainloop(
    const GemmCtx& cx, float acc[4][4][4])
{
    auto load_chunk = [&](int ci, int st) {
        if (cx.gsrc) {
            const uint32_t tb = cx.sbase + st * STAGE_B + cx.smoff;
            #pragma unroll
            for (int i = 0; i < 16; i++) {
                const int r = cx.lr0 + i * 8;
                const uint32_t dst = tb + SWG(r, cx.lch);
                cp_async16(dst, cx.gsrc + (size_t)(cx.row0 + r) * 2048 + ci * KCH + cx.lch * 8);
            }
        }
        asm volatile("cp.async.commit_group;\n" ::: "memory");
    };

    load_chunk(0, 0);

    for (int ci = 0; ci < NCHUNKS; ci++) {
        asm volatile("cp.async.wait_group 0;\n" ::: "memory");
        __syncthreads();
        if (ci + 1 < NCHUNKS) load_chunk(ci + 1, (ci + 1) & 1);

        const uint32_t ah_b = cx.sbase + (ci & 1) * STAGE_B;
        const uint32_t bh_b = ah_b + TILE_B;
        const uint32_t bl_b = ah_b + 2 * TILE_B;

        #pragma unroll
        for (int ks = 0; ks < 4; ks++) {
            uint32_t a4[4][4];
            #pragma unroll
            for (int mi = 0; mi < 4; mi++) {
                const int r = cx.m0w + mi * 16 + cx.a_row;
                ldsm_x4(a4[mi][0], a4[mi][1], a4[mi][2], a4[mi][3],
                        ah_b + SWG(r, ks * 2 + cx.a_kh));
            }
            uint32_t bh[4][2], bl[4][2];
            #pragma unroll
            for (int jb = 0; jb < 2; jb++) {
                const int r = cx.n0w + jb * 16 + cx.b_row;
                const uint32_t off = SWG(r, ks * 2 + cx.b_kh);
                ldsm_x4(bh[2*jb][0], bh[2*jb][1], bh[2*jb+1][0], bh[2*jb+1][1], bh_b + off);
                ldsm_x4(bl[2*jb][0], bl[2*jb][1], bl[2*jb+1][0], bl[2*jb+1][1], bl_b + off);
            }
            // Pass 1: Ah*Bh (16 independent accumulators)
            #pragma unroll
            for (int mi = 0; mi < 4; mi++)
                #pragma unroll
                for (int nj = 0; nj < 4; nj++) {
                    float* cc = acc[mi][nj];
                    mma16816(cc[0], cc[1], cc[2], cc[3],
                             a4[mi][0], a4[mi][1], a4[mi][2], a4[mi][3],
                             bh[nj][0], bh[nj][1]);
                }
            // Pass 2: Ah*Bl
            #pragma unroll
            for (int mi = 0; mi < 4; mi++)
                #pragma unroll
                for (int nj = 0; nj < 4; nj++) {
                    float* cc = acc[mi][nj];
                    mma16816(cc[0], cc[1], cc[2], cc[3],
                             a4[mi][0], a4[mi][1], a4[mi][2], a4[mi][3],
                             bl[nj][0], bl[nj][1]);
                }
        }
    }
}

__device__ __forceinline__ void gemm_init_ctx(
    GemmCtx& cx, uint32_t sbase, int tid, int m0, int n0,
    const __half* Ah, const __half* Bh, const __half* Bl)
{
    cx.sbase = sbase;
    const int tt = tid >> 6;
    const int t6 = tid & 63;
    cx.lch = t6 & 7;
    cx.lr0 = t6 >> 3;
    switch (tt) {
        case 0:  cx.gsrc = Ah; cx.row0 = m0; cx.smoff = 0;          break;
        case 1:  cx.gsrc = Bh; cx.row0 = n0; cx.smoff = TILE_B;     break;
        case 2:  cx.gsrc = Bl; cx.row0 = n0; cx.smoff = 2*TILE_B;   break;
        default: cx.gsrc = nullptr; cx.row0 = 0; cx.smoff = 0;      break;
    }
    const int wid = tid >> 5, lane = tid & 31;
    cx.m0w = (wid & 1) * 64;
    cx.n0w = (wid >> 1) * 32;
    cx.a_row = lane & 15;
    cx.a_kh  = lane >> 4;
    cx.b_row = (lane & 7) + ((lane >> 4) & 1) * 8;
    cx.b_kh  = (lane >> 3) & 1;
}

// ---------------------------------------------------------------------------
// Plain GEMM (fp32 C output) — output projection.
// ---------------------------------------------------------------------------
__global__ __launch_bounds__(256, 2)
void gemm_mma(const __half* __restrict__ Ah,
              const __half* __restrict__ Bh, const __half* __restrict__ Bl,
              float* __restrict__ C, int ldc)
{
    extern __shared__ char dsm[];
    const int tid = threadIdx.x;
    const int lane = tid & 31;
    const int m0 = blockIdx.y * 128;
    const int n0 = blockIdx.x * 128;

    GemmCtx cx;
    gemm_init_ctx(cx, smem_u32(dsm), tid, m0, n0, Ah, Bh, Bl);

    float acc[4][4][4];
    #pragma unroll
    for (int i = 0; i < 4; i++)
        #pragma unroll
        for (int j = 0; j < 4; j++)
            #pragma unroll
            for (int q = 0; q < 4; q++) acc[i][j][q] = 0.0f;

    gemm_mainloop(cx, acc);

    const int er = lane >> 2;
    const int ec = (lane & 3) * 2;
    #pragma unroll
    for (int mi = 0; mi < 4; mi++) {
        const int row_a = m0 + cx.m0w + mi * 16 + er;
        #pragma unroll
        for (int nj = 0; nj < 4; nj++) {
            const int col = n0 + cx.n0w + nj * 8 + ec;
            float* cc = acc[mi][nj];
            *reinterpret_cast<float2*>(C + (size_t)row_a * ldc + col) =
                make_float2(cc[0], cc[1]);
            *reinterpret_cast<float2*>(C + (size_t)(row_a + 8) * ldc + col) =
                make_float2(cc[2], cc[3]);
        }
    }
}

// ---------------------------------------------------------------------------
// QKV GEMM with fused RoPE + scale + fp16 split epilogue.
// ---------------------------------------------------------------------------
__global__ __launch_bounds__(256, 2)
void gemm_qkv_fused(const __half* __restrict__ Ah,
                    const __half* __restrict__ Bh, const __half* __restrict__ Bl,
                    __half* __restrict__ Qh,
                    __half* __restrict__ Kh, __half* __restrict__ Kl,
                    __half* __restrict__ Vh, __half* __restrict__ Vl)
{
    extern __shared__ char dsm[];
    const int tid = threadIdx.x;
    const int lane = tid & 31;
    const int m0 = blockIdx.y * 128;
    const int n0 = blockIdx.x * 128;

    GemmCtx cx;
    gemm_init_ctx(cx, smem_u32(dsm), tid, m0, n0, Ah, Bh, Bl);

    float acc[4][4][4];
    #pragma unroll
    for (int i = 0; i < 4; i++)
        #pragma unroll
        for (int j = 0; j < 4; j++)
            #pragma unroll
            for (int q = 0; q < 4; q++) acc[i][j][q] = 0.0f;

    gemm_mainloop(cx, acc);

    // ---- stage fp32 tile to smem [128][132] (67.6KB <= 96KB) ----
    __syncthreads();
    float* ft = reinterpret_cast<float*>(dsm);
    const int er = lane >> 2;
    const int ec = (lane & 3) * 2;
    #pragma unroll
    for (int mi = 0; mi < 4; mi++) {
        const int r = cx.m0w + mi * 16 + er;
        #pragma unroll
        for (int nj = 0; nj < 4; nj++) {
            const int c = cx.n0w + nj * 8 + ec;
            float* cc = acc[mi][nj];
            *reinterpret_cast<float2*>(ft + r * 132 + c)       = make_float2(cc[0], cc[1]);
            *reinterpret_cast<float2*>(ft + (r + 8) * 132 + c) = make_float2(cc[2], cc[3]);
        }
    }
    __syncthreads();

    // ---- fused epilogue by region ----
    if (n0 < QCOLS) {
        const int head = n0 >> 7;
        const float scale = 0.08838834764831845f;
        for (int it = 0; it < 32; it++) {
            const int idx = tid + it * 256;
            const int r = idx >> 6, i = idx & 63;
            const int grow = m0 + r;
            const int pos = grow & (SEQ - 1);
            const float x1 = ft[r * 132 + i];
            const float x2 = ft[r * 132 + i + 64];
            const float c = g_cos[pos * 64 + i];
            const float s = g_sin[pos * 64 + i];
            const float y1 = (x1 * c - x2 * s) * scale;
            const float y2 = (x2 * c + x1 * s) * scale;
            const size_t o = (size_t)grow * QCOLS + head * HDIM + i;
            Qh[o]      = __float2half_rn(y1);
            Qh[o + 64] = __float2half_rn(y2);
        }
    } else if (n0 < QCOLS + KCOLS) {
        const int head = (n0 - QCOLS) >> 7;
        for (int it = 0; it < 32; it++) {
            const int idx = tid + it * 256;
            const int r = idx >> 6, i = idx & 63;
            const int grow = m0 + r;
            const int pos = grow & (SEQ - 1);
            const float x1 = ft[r * 132 + i];
            const float x2 = ft[r * 132 + i + 64];
            const float c = g_cos[pos * 64 + i];
            const float s = g_sin[pos * 64 + i];
            const float y1 = x1 * c - x2 * s;
            const float y2 = x2 * c + x1 * s;
            const __half h1 = __float2half_rn(y1);
            const __half h2 = __float2half_rn(y2);
            const size_t o = (size_t)grow * KCOLS + head * HDIM + i;
            Kh[o]      = h1;
            Kh[o + 64] = h2;
            Kl[o]      = __float2half_rn(y1 - __half2float(h1));
            Kl[o + 64] = __float2half_rn(y2 - __half2float(h2));
        }
    } else {
        const int cbase = n0 - (QCOLS + KCOLS);
        for (int it = 0; it < 64; it++) {
            const int idx = tid + it * 256;
            const int r = idx >> 7, c = idx & 127;
            const int grow = m0 + r;
            const float x = ft[r * 132 + c];
            const __half h = __float2half_rn(x);
            const size_t o = (size_t)grow * KCOLS + cbase + c;
            Vh[o] = h;
            Vl[o] = __float2half_rn(x - __half2float(h));
        }
    }
}

// ---------------------------------------------------------------------------
// Flash attention, fp16 2-product. FKT=32 keys/tile, DOUBLE-buffered KV,
// 96KB smem -> 2 CTAs/SM: prefetch inside the CTA, softmax/sync bubbles
// covered by the co-resident CTA. qt descending. Writes ctx hi only.
// ---------------------------------------------------------------------------
#define FQT 128
#define FKT 32
#define FQ_B    32768
#define FTILE_B 8192                        // 32 rows x 256B
#define FKV_B   (4*FTILE_B)                 // Kh,Kl,Vh,Vl per stage = 32KB
#define FLASH_SMEM (FQ_B + 2*FKV_B)         // 96KB

__global__ __launch_bounds__(256, 2)
void flash_mma(const __half* __restrict__ Qh_g,
               const __half* __restrict__ Kh_g, const __half* __restrict__ Kl_g,
               const __half* __restrict__ Vh_g, const __half* __restrict__ Vl_g,
               __half* __restrict__ Ch_g)
{
    extern __shared__ char dsm[];
    const uint32_t sb = smem_u32(dsm);
    const uint32_t Qh_s = sb;
    const uint32_t KV_s = sb + FQ_B;

    const int tid = threadIdx.x;
    const int w = tid >> 5, lane = tid & 31;
    const int qt = gridDim.x - 1 - blockIdx.x;
    const int h = blockIdx.y, b = blockIdx.z;
    const int kvh = h >> 2;
    const int qrow0 = b * SEQ + qt * FQT;
    const int nkt = 4 * qt + 4;

    {
        const int c = tid & 15, r0 = tid >> 4;
        #pragma unroll
        for (int i = 0; i < 8; i++) {
            const int r = r0 + i * 16;
            const size_t go = (size_t)(qrow0 + r) * QCOLS + h * HDIM + c * 8;
            cp_async16(Qh_s + SW(r, c), Qh_g + go);
        }
    }

    auto load_kv = [&](int kt, int st) {
        const int c = tid & 15, r0 = tid >> 4;
        const uint32_t base = KV_s + st * FKV_B;
        const int krow0 = b * SEQ + kt * FKT;
        #pragma unroll
        for (int i = 0; i < 2; i++) {
            const int r = r0 + i * 16;
            const size_t go = (size_t)(krow0 + r) * KCOLS + kvh * HDIM + c * 8;
            cp_async16(base +             SW(r, c), Kh_g + go);
            cp_async16(base +   FTILE_B + SW(r, c), Kl_g + go);
            cp_async16(base + 2*FTILE_B + SW(r, c), Vh_g + go);
            cp_async16(base + 3*FTILE_B + SW(r, c), Vl_g + go);
        }
        asm volatile("cp.async.commit_group;\n" ::: "memory");
    };

    load_kv(0, 0);
    asm volatile("cp.async.commit_group;\n" ::: "memory");  // empty group (Q rides group 0)

    const int er = lane >> 2, ec = lane & 3;
    const int a_row = w * 16 + (lane & 15);
    const int a_kh  = lane >> 4;
    const int b_n   = (lane & 7) + ((lane >> 4) & 1) * 8;
    const int b_kh  = (lane >> 3) & 1;
    const int v_key = (lane & 7) + ((lane >> 3) & 1) * 8;
    const int v_dc  = lane >> 4;

    const int rg0 = qt * FQT + w * 16 + er;
    const int rg1 = rg0 + 8;

    float o[16][4];
    #pragma unroll
    for (int j = 0; j < 16; j++)
        #pragma unroll
        for (int q = 0; q < 4; q++) o[j][q] = 0.0f;
    float m0 = -1e30f, m1 = -1e30f, l0 = 0.0f, l1 = 0.0f;

    for (int kt = 0; kt < nkt; kt++) {
        const int st = kt & 1;
        if (kt + 1 < nkt) {
            load_kv(kt + 1, (kt + 1) & 1);
            asm volatile("cp.async.wait_group 1;\n" ::: "memory");
        } else {
            asm volatile("cp.async.wait_group 0;\n" ::: "memory");
        }
        __syncthreads();

        const uint32_t Kh_s = KV_s + st * FKV_B;
        const uint32_t Kl_s = Kh_s + FTILE_B;
        const uint32_t Vh_s = Kh_s + 2 * FTILE_B;
        const uint32_t Vl_s = Kh_s + 3 * FTILE_B;

        float s[4][4];
        #pragma unroll
        for (int f = 0; f < 4; f++)
            #pragma unroll
            for (int q = 0; q < 4; q++) s[f][q] = 0.0f;

        #pragma unroll
        for (int ks = 0; ks < 8; ks++) {
            uint32_t qa[4];
            ldsm_x4(qa[0], qa[1], qa[2], qa[3], Qh_s + SW(a_row, ks*2 + a_kh));
            #pragma unroll
            for (int ng = 0; ng < 2; ng++) {
                uint32_t kh0, kh1, kh2, kh3, kl0, kl1, kl2, kl3;
                ldsm_x4(kh0, kh1, kh2, kh3, Kh_s + SW(ng*16 + b_n, ks*2 + b_kh));
                ldsm_x4(kl0, kl1, kl2, kl3, Kl_s + SW(ng*16 + b_n, ks*2 + b_kh));
                float* s0 = s[ng*2];
                float* s1 = s[ng*2 + 1];
                mma16816(s0[0], s0[1], s0[2], s0[3], qa[0], qa[1], qa[2], qa[3], kh0, kh1);
                mma16816(s1[0], s1[1], s1[2], s1[3], qa[0], qa[1], qa[2], qa[3], kh2, kh3);
                mma16816(s0[0], s0[1], s0[2], s0[3], qa[0], qa[1], qa[2], qa[3], kl0, kl1);
                mma16816(s1[0], s1[1], s1[2], s1[3], qa[0], qa[1], qa[2], qa[3], kl2, kl3);
            }
        }

        if (kt >= 4 * qt) {
            #pragma unroll
            for (int f = 0; f < 4; f++) {
                const int key0 = kt * FKT + f * 8 + ec * 2;
                if (key0     > rg0) s[f][0] = -1e30f;
                if (key0 + 1 > rg0) s[f][1] = -1e30f;
                if (key0     > rg1) s[f][2] = -1e30f;
                if (key0 + 1 > rg1) s[f][3] = -1e30f;
            }
        }

        float nm0 = -1e30f, nm1 = -1e30f;
        #pragma unroll
        for (int f = 0; f < 4; f++) {
            nm0 = fmaxf(nm0, fmaxf(s[f][0], s[f][1]));
            nm1 = fmaxf(nm1, fmaxf(s[f][2], s[f][3]));
        }
        nm0 = fmaxf(nm0, __shfl_xor_sync(0xffffffffu, nm0, 1));
        nm0 = fmaxf(nm0, __shfl_xor_sync(0xffffffffu, nm0, 2));
        nm1 = fmaxf(nm1, __shfl_xor_sync(0xffffffffu, nm1, 1));
        nm1 = fmaxf(nm1, __shfl_xor_sync(0xffffffffu, nm1, 2));
        nm0 = fmaxf(nm0, m0);
        nm1 = fmaxf(nm1, m1);
        const float corr0 = __expf(m0 - nm0);
        const float corr1 = __expf(m1 - nm1);
        m0 = nm0;
        m1 = nm1;

        float rs0 = 0.0f, rs1 = 0.0f;
        #pragma unroll
        for (int f = 0; f < 4; f++) {
            s[f][0] = __expf(s[f][0] - nm0);
            s[f][1] = __expf(s[f][1] - nm0);
            s[f][2] = __expf(s[f][2] - nm1);
            s[f][3] = __expf(s[f][3] - nm1);
            rs0 += s[f][0] + s[f][1];
            rs1 += s[f][2] + s[f][3];
        }
        rs0 += __shfl_xor_sync(0xffffffffu, rs0, 1);
        rs0 += __shfl_xor_sync(0xffffffffu, rs0, 2);
        rs1 += __shfl_xor_sync(0xffffffffu, rs1, 1);
        rs1 += __shfl_xor_sync(0xffffffffu, rs1, 2);
        l0 = l0 * corr0 + rs0;
        l1 = l1 * corr1 + rs1;
        #pragma unroll
        for (int j = 0; j < 16; j++) {
            o[j][0] *= corr0; o[j][1] *= corr0;
            o[j][2] *= corr1; o[j][3] *= corr1;
        }

        #pragma unroll
        for (int kp = 0; kp < 2; kp++) {
            const float* f0 = s[2*kp];
            const float* f1 = s[2*kp + 1];
            uint32_t pa[4];
            __half2 t;
            t = __floats2half2_rn(f0[0], f0[1]); pa[0] = *reinterpret_cast<uint32_t*>(&t);
            t = __floats2half2_rn(f0[2], f0[3]); pa[1] = *reinterpret_cast<uint32_t*>(&t);
            t = __floats2half2_rn(f1[0], f1[1]); pa[2] = *reinterpret_cast<uint32_t*>(&t);
            t = __floats2half2_rn(f1[2], f1[3]); pa[3] = *reinterpret_cast<uint32_t*>(&t);

            #pragma unroll
            for (int nd = 0; nd < 8; nd++) {
                uint32_t vh0, vh1, vh2, vh3, vl0, vl1, vl2, vl3;
                ldsm_x4t(vh0, vh1, vh2, vh3, Vh_s + SW(kp*16 + v_key, nd*2 + v_dc));
                ldsm_x4t(vl0, vl1, vl2, vl3, Vl_s + SW(kp*16 + v_key, nd*2 + v_dc));
                float* o0 = o[nd*2];
                float* o1 = o[nd*2 + 1];
                mma16816(o0[0], o0[1], o0[2], o0[3], pa[0], pa[1], pa[2], pa[3], vh0, vh1);
                mma16816(o1[0], o1[1], o1[2], o1[3], pa[0], pa[1], pa[2], pa[3], vh2, vh3);
                mma16816(o0[0], o0[1], o0[2], o0[3], pa[0], pa[1], pa[2], pa[3], vl0, vl1);
                mma16816(o1[0], o1[1], o1[2], o1[3], pa[0], pa[1], pa[2], pa[3], vl2, vl3);
            }
        }
        __syncthreads();   // all reads of stage st done -> safe for load(kt+2)
    }

    const float inv0 = 1.0f / l0;
    const float inv1 = 1.0f / l1;
    const size_t row0 = (size_t)(qrow0 + w * 16 + er);
    const size_t row1 = row0 + 8;
    #pragma unroll
    for (int j = 0; j < 16; j++) {
        const int col = h * HDIM + j * 8 + ec * 2;
        *reinterpret_cast<__half2*>(Ch_g + row0 * QCOLS + col) =
            __floats2half2_rn(o[j][0] * inv0, o[j][1] * inv0);
        *reinterpret_cast<__half2*>(Ch_g + row1 * QCOLS + col) =
            __floats2half2_rn(o[j][2] * inv1, o[j][3] * inv1);
    }
}

// ---------------------------------------------------------------------------
extern "C" void kernel_launch(void* const* d_in, const int* in_sizes, int n_in,
                              void* d_out, int out_size)
{
    const float* hidden = (const float*)d_in[0];
    const float* Wq = (const float*)d_in[1];
    const float* Wk = (const float*)d_in[2];
    const float* Wv = (const float*)d_in[3];
    const float* Wo = (const float*)d_in[4];
    float* out = (float*)d_out;

    __half *ah, *ch, *qh, *kh, *kl, *vh, *vl, *wh, *wl, *woh, *wol;
    cudaGetSymbolAddress((void**)&ah, g_ah);
    cudaGetSymbolAddress((void**)&ch, g_ch);
    cudaGetSymbolAddress((void**)&qh, g_qh);
    cudaGetSymbolAddress((void**)&kh, g_kh);  cudaGetSymbolAddress((void**)&kl, g_kl);
    cudaGetSymbolAddress((void**)&vh, g_vh);  cudaGetSymbolAddress((void**)&vl, g_vl);
    cudaGetSymbolAddress((void**)&wh, g_wh);  cudaGetSymbolAddress((void**)&wl, g_wl);
    cudaGetSymbolAddress((void**)&woh, g_woh); cudaGetSymbolAddress((void**)&wol, g_wol);

    cudaFuncSetAttribute(gemm_mma,
                         cudaFuncAttributeMaxDynamicSharedMemorySize, GEMM_SMEM);
    cudaFuncSetAttribute(gemm_qkv_fused,
                         cudaFuncAttributeMaxDynamicSharedMemorySize, GEMM_SMEM);
    cudaFuncSetAttribute(flash_mma,
                         cudaFuncAttributeMaxDynamicSharedMemorySize, FLASH_SMEM);

    // 1) RoPE table, 2) hidden hi-split, 3) all weight transposes (one launch)
    rope_table_kernel<<<(SEQ*64 + 255)/256, 256>>>();
    split_hi_kernel<<<(ROWS*HID/4 + 255)/256, 256>>>(hidden, ah, ROWS*HID/4);
    tsplit_all_kernel<<<10240, dim3(32,8)>>>(Wq, Wk, Wv, Wo, wh, wl, woh, wol);

    // 4) Merged QKV projection with fused RoPE/scale/split epilogue
    gemm_qkv_fused<<<dim3(QKVC/128, ROWS/128), 256, GEMM_SMEM>>>(
        ah, wh, wl, qh, kh, kl, vh, vl);

    // 5) Attention, writes ctx hi directly
    flash_mma<<<dim3(SEQ/FQT, NHQ, BATCH), 256, FLASH_SMEM>>>(qh, kh, kl, vh, vl, ch);

    // 6) Output projection
    gemm_mma<<<dim3(HID/128, ROWS/128), 256, GEMM_SMEM>>>(ch, woh, wol, out, HID);
}

// round 14
// speedup vs baseline: 1.1199x; 1.1149x over previous
#include <cuda_runtime.h>
#include <cuda_fp16.h>
#include <math.h>
#include <stdint.h>

// Problem constants
#define BATCH 2
#define SEQ   2048
#define HID   2048
#define NHQ   16
#define NKV   4
#define HDIM  128
#define ROWS  (BATCH*SEQ)          // 4096
#define QCOLS (NHQ*HDIM)           // 2048
#define KCOLS (NKV*HDIM)           // 512
#define QKVC  (QCOLS + 2*KCOLS)    // 3072

// ---------------------------------------------------------------------------
// Device scratch (static — no allocation allowed)
// ---------------------------------------------------------------------------
__device__ float g_cos[SEQ*64];
__device__ float g_sin[SEQ*64];

__device__ __half g_ah[ROWS*HID];                       // hidden (hi only)
__device__ __half g_ch[ROWS*QCOLS];                     // ctx (hi only)
__device__ __half g_qh[ROWS*QCOLS];                     // q (hi only, rope+scale)
__device__ __half g_kh[ROWS*KCOLS], g_kl[ROWS*KCOLS];   // k hi/lo (rope)
__device__ __half g_vh[ROWS*KCOLS];                     // v hi only
__device__ __half g_wh[QKVC*HID],   g_wl[QKVC*HID];     // [Wq;Wk;Wv]^T hi/lo
__device__ __half g_woh[HID*QCOLS], g_wol[HID*QCOLS];   // Wo^T hi/lo

// ---------------------------------------------------------------------------
// Helpers
// ---------------------------------------------------------------------------
__device__ __forceinline__ uint32_t smem_u32(const void* p) {
    uint32_t a;
    asm("{ .reg .u64 t; cvta.to.shared.u64 t, %1; cvt.u32.u64 %0, t; }" : "=r"(a) : "l"(p));
    return a;
}
__device__ __forceinline__ void cp_async16(uint32_t dst, const void* src) {
    asm volatile("cp.async.cg.shared.global [%0], [%1], 16;\n" :: "r"(dst), "l"(src) : "memory");
}
__device__ __forceinline__ void ldsm_x4(uint32_t& r0, uint32_t& r1, uint32_t& r2, uint32_t& r3,
                                        uint32_t addr) {
    asm volatile("ldmatrix.sync.aligned.m8n8.x4.shared.b16 {%0,%1,%2,%3}, [%4];"
                 : "=r"(r0), "=r"(r1), "=r"(r2), "=r"(r3) : "r"(addr));
}
__device__ __forceinline__ void ldsm_x4t(uint32_t& r0, uint32_t& r1, uint32_t& r2, uint32_t& r3,
                                         uint32_t addr) {
    asm volatile("ldmatrix.sync.aligned.m8n8.x4.trans.shared.b16 {%0,%1,%2,%3}, [%4];"
                 : "=r"(r0), "=r"(r1), "=r"(r2), "=r"(r3) : "r"(addr));
}
__device__ __forceinline__ void mma16816(float& c0, float& c1, float& c2, float& c3,
                                         uint32_t a0, uint32_t a1, uint32_t a2, uint32_t a3,
                                         uint32_t b0, uint32_t b1) {
    asm volatile(
        "mma.sync.aligned.m16n8k16.row.col.f32.f16.f16.f32 "
        "{%0,%1,%2,%3}, {%4,%5,%6,%7}, {%8,%9}, {%0,%1,%2,%3};"
        : "+f"(c0), "+f"(c1), "+f"(c2), "+f"(c3)
        : "r"(a0), "r"(a1), "r"(a2), "r"(a3), "r"(b0), "r"(b1));
}
// flash smem swizzle: row r (256B rows of fp16[128]), 16B chunk c (0..15)
#define SW(r, c) ((uint32_t)((r) * 256 + (((c) ^ ((r) & 7)) << 4)))
// gemm smem swizzle: row r (128B rows of fp16[64]), 16B chunk c (0..7)
#define SWG(r, c) ((uint32_t)((r) * 128 + (((c) ^ ((r) & 7)) << 4)))

// ---------------------------------------------------------------------------
// fp32 -> fp16 hi (row-major, same layout)
// ---------------------------------------------------------------------------
__global__ void split_hi_kernel(const float* __restrict__ in,
                                __half* __restrict__ hi, int n4)
{
    int i = blockIdx.x * blockDim.x + threadIdx.x;
    if (i >= n4) return;
    float4 v = reinterpret_cast<const float4*>(in)[i];
    __half2* hp = reinterpret_cast<__half2*>(hi);
    hp[2*i]   = __floats2half2_rn(v.x, v.y);
    hp[2*i+1] = __floats2half2_rn(v.z, v.w);
}

// All four weight transposes+splits (fp16 hi/lo) in ONE launch.
__global__ void tsplit_all_kernel(const float* __restrict__ Wq, const float* __restrict__ Wk,
                                  const float* __restrict__ Wv, const float* __restrict__ Wo,
                                  __half* __restrict__ wh, __half* __restrict__ wl,
                                  __half* __restrict__ woh, __half* __restrict__ wol)
{
    __shared__ float t[32][33];
    const int bid = blockIdx.x;
    const float* src;
    __half *dh, *dl;
    int Nin, nbx, tile;
    if (bid < 4096)      { src = Wq; dh = wh; dl = wl; Nin = 2048; nbx = 64; tile = bid; }
    else if (bid < 5120) { src = Wk; dh = wh + (size_t)QCOLS*HID; dl = wl + (size_t)QCOLS*HID;
                           Nin = 512; nbx = 16; tile = bid - 4096; }
    else if (bid < 6144) { src = Wv; dh = wh + (size_t)(QCOLS+KCOLS)*HID; dl = wl + (size_t)(QCOLS+KCOLS)*HID;
                           Nin = 512; nbx = 16; tile = bid - 5120; }
    else                 { src = Wo; dh = woh; dl = wol; Nin = 2048; nbx = 64; tile = bid - 6144; }

    const int tx = threadIdx.x, ty = threadIdx.y;
    const int n0 = (tile % nbx) * 32, k0 = (tile / nbx) * 32;
    #pragma unroll
    for (int j = 0; j < 32; j += 8)
        t[ty + j][tx] = src[(size_t)(k0 + ty + j) * Nin + n0 + tx];
    __syncthreads();
    #pragma unroll
    for (int j = 0; j < 32; j += 8) {
        float x = t[tx][ty + j];
        __half h = __float2half_rn(x);
        __half l = __float2half_rn(x - __half2float(h));
        size_t o = (size_t)(n0 + ty + j) * 2048 + k0 + tx;
        dh[o] = h;
        dl[o] = l;
    }
}

// ---------------------------------------------------------------------------
// RoPE table
// ---------------------------------------------------------------------------
__global__ void rope_table_kernel()
{
    int idx = blockIdx.x * blockDim.x + threadIdx.x;
    if (idx >= SEQ * 64) return;
    int pos = idx >> 6, i = idx & 63;
    double inv = exp2(-(double)i * (13.287712379549449 / 64.0));
    double ang = (double)pos * inv;
    const double twopi = 6.283185307179586476925286766559;
    ang -= floor(ang * (1.0 / twopi)) * twopi;
    if (ang > 3.14159265358979323846) ang -= twopi;
    float s, c;
    sincosf((float)ang, &s, &c);
    g_cos[idx] = c;
    g_sin[idx] = s;
}

// ---------------------------------------------------------------------------
// GEMM mainloop: 128x128 CTA tile, fp16 2-product (Ah*Bh + Ah*Bl).
// KCH=64 (32 chunks), 2-stage double buffer, one sync per chunk, 2 CTAs/SM.
// ---------------------------------------------------------------------------
#define KCH       64
#define NCHUNKS   32
#define TILE_B    16384           // 128 rows x 128 B
#define STAGE_B   (3*TILE_B)      // 48 KB
#define NSTG      2
#define GEMM_SMEM (NSTG*STAGE_B)  // 96 KB

struct GemmCtx {
    uint32_t sbase;
    const __half* gsrc;
    int row0, lch, lr0;
    uint32_t smoff;
    int m0w, n0w;
    int a_row, a_kh, b_row, b_kh;
};

__device__ __forceinline__ void gemm_mainloop(
    const GemmCtx& cx, float acc[4][4][4])
{
    auto load_chunk = [&](int ci, int st) {
        if (cx.gsrc) {
            const uint32_t tb = cx.sbase + st * STAGE_B + cx.smoff;
            #pragma unroll
            for (int i = 0; i < 16; i++) {
                const int r = cx.lr0 + i * 8;
                const uint32_t dst = tb + SWG(r, cx.lch);
                cp_async16(dst, cx.gsrc + (size_t)(cx.row0 + r) * 2048 + ci * KCH + cx.lch * 8);
            }
        }
        asm volatile("cp.async.commit_group;\n" ::: "memory");
    };

    load_chunk(0, 0);

    for (int ci = 0; ci < NCHUNKS; ci++) {
        asm volatile("cp.async.wait_group 0;\n" ::: "memory");
        __syncthreads();
        if (ci + 1 < NCHUNKS) load_chunk(ci + 1, (ci + 1) & 1);

        const uint32_t ah_b = cx.sbase + (ci & 1) * STAGE_B;
        const uint32_t bh_b = ah_b + TILE_B;
        const uint32_t bl_b = ah_b + 2 * TILE_B;

        #pragma unroll
        for (int ks = 0; ks < 4; ks++) {
            uint32_t a4[4][4];
            #pragma unroll
            for (int mi = 0; mi < 4; mi++) {
                const int r = cx.m0w + mi * 16 + cx.a_row;
                ldsm_x4(a4[mi][0], a4[mi][1], a4[mi][2], a4[mi][3],
                        ah_b + SWG(r, ks * 2 + cx.a_kh));
            }
            uint32_t bh[4][2], bl[4][2];
            #pragma unroll
            for (int jb = 0; jb < 2; jb++) {
                const int r = cx.n0w + jb * 16 + cx.b_row;
                const uint32_t off = SWG(r, ks * 2 + cx.b_kh);
                ldsm_x4(bh[2*jb][0], bh[2*jb][1], bh[2*jb+1][0], bh[2*jb+1][1], bh_b + off);
                ldsm_x4(bl[2*jb][0], bl[2*jb][1], bl[2*jb+1][0], bl[2*jb+1][1], bl_b + off);
            }
            #pragma unroll
            for (int mi = 0; mi < 4; mi++)
                #pragma unroll
                for (int nj = 0; nj < 4; nj++) {
                    float* cc = acc[mi][nj];
                    mma16816(cc[0], cc[1], cc[2], cc[3],
                             a4[mi][0], a4[mi][1], a4[mi][2], a4[mi][3],
                             bh[nj][0], bh[nj][1]);
                }
            #pragma unroll
            for (int mi = 0; mi < 4; mi++)
                #pragma unroll
                for (int nj = 0; nj < 4; nj++) {
                    float* cc = acc[mi][nj];
                    mma16816(cc[0], cc[1], cc[2], cc[3],
                             a4[mi][0], a4[mi][1], a4[mi][2], a4[mi][3],
                             bl[nj][0], bl[nj][1]);
                }
        }
    }
}

__device__ __forceinline__ void gemm_init_ctx(
    GemmCtx& cx, uint32_t sbase, int tid, int m0, int n0,
    const __half* Ah, const __half* Bh, const __half* Bl)
{
    cx.sbase = sbase;
    const int tt = tid >> 6;
    const int t6 = tid & 63;
    cx.lch = t6 & 7;
    cx.lr0 = t6 >> 3;
    switch (tt) {
        case 0:  cx.gsrc = Ah; cx.row0 = m0; cx.smoff = 0;          break;
        case 1:  cx.gsrc = Bh; cx.row0 = n0; cx.smoff = TILE_B;     break;
        case 2:  cx.gsrc = Bl; cx.row0 = n0; cx.smoff = 2*TILE_B;   break;
        default: cx.gsrc = nullptr; cx.row0 = 0; cx.smoff = 0;      break;
    }
    const int wid = tid >> 5, lane = tid & 31;
    cx.m0w = (wid & 1) * 64;
    cx.n0w = (wid >> 1) * 32;
    cx.a_row = lane & 15;
    cx.a_kh  = lane >> 4;
    cx.b_row = (lane & 7) + ((lane >> 4) & 1) * 8;
    cx.b_kh  = (lane >> 3) & 1;
}

// ---------------------------------------------------------------------------
// Plain GEMM (fp32 C output) — output projection.
// ---------------------------------------------------------------------------
__global__ __launch_bounds__(256, 2)
void gemm_mma(const __half* __restrict__ Ah,
              const __half* __restrict__ Bh, const __half* __restrict__ Bl,
              float* __restrict__ C, int ldc)
{
    extern __shared__ char dsm[];
    const int tid = threadIdx.x;
    const int lane = tid & 31;
    const int m0 = blockIdx.y * 128;
    const int n0 = blockIdx.x * 128;

    GemmCtx cx;
    gemm_init_ctx(cx, smem_u32(dsm), tid, m0, n0, Ah, Bh, Bl);

    float acc[4][4][4];
    #pragma unroll
    for (int i = 0; i < 4; i++)
        #pragma unroll
        for (int j = 0; j < 4; j++)
            #pragma unroll
            for (int q = 0; q < 4; q++) acc[i][j][q] = 0.0f;

    gemm_mainloop(cx, acc);

    const int er = lane >> 2;
    const int ec = (lane & 3) * 2;
    #pragma unroll
    for (int mi = 0; mi < 4; mi++) {
        const int row_a = m0 + cx.m0w + mi * 16 + er;
        #pragma unroll
        for (int nj = 0; nj < 4; nj++) {
            const int col = n0 + cx.n0w + nj * 8 + ec;
            float* cc = acc[mi][nj];
            *reinterpret_cast<float2*>(C + (size_t)row_a * ldc + col) =
                make_float2(cc[0], cc[1]);
            *reinterpret_cast<float2*>(C + (size_t)(row_a + 8) * ldc + col) =
                make_float2(cc[2], cc[3]);
        }
    }
}

// ---------------------------------------------------------------------------
// QKV GEMM with fused RoPE + scale + fp16 split epilogue.
// Q: hi only (+scale).  K: hi/lo.  V: hi only.
// ---------------------------------------------------------------------------
__global__ __launch_bounds__(256, 2)
void gemm_qkv_fused(const __half* __restrict__ Ah,
                    const __half* __restrict__ Bh, const __half* __restrict__ Bl,
                    __half* __restrict__ Qh,
                    __half* __restrict__ Kh, __half* __restrict__ Kl,
                    __half* __restrict__ Vh)
{
    extern __shared__ char dsm[];
    const int tid = threadIdx.x;
    const int lane = tid & 31;
    const int m0 = blockIdx.y * 128;
    const int n0 = blockIdx.x * 128;

    GemmCtx cx;
    gemm_init_ctx(cx, smem_u32(dsm), tid, m0, n0, Ah, Bh, Bl);

    float acc[4][4][4];
    #pragma unroll
    for (int i = 0; i < 4; i++)
        #pragma unroll
        for (int j = 0; j < 4; j++)
            #pragma unroll
            for (int q = 0; q < 4; q++) acc[i][j][q] = 0.0f;

    gemm_mainloop(cx, acc);

    // ---- stage fp32 tile to smem [128][132] ----
    __syncthreads();
    float* ft = reinterpret_cast<float*>(dsm);
    const int er = lane >> 2;
    const int ec = (lane & 3) * 2;
    #pragma unroll
    for (int mi = 0; mi < 4; mi++) {
        const int r = cx.m0w + mi * 16 + er;
        #pragma unroll
        for (int nj = 0; nj < 4; nj++) {
            const int c = cx.n0w + nj * 8 + ec;
            float* cc = acc[mi][nj];
            *reinterpret_cast<float2*>(ft + r * 132 + c)       = make_float2(cc[0], cc[1]);
            *reinterpret_cast<float2*>(ft + (r + 8) * 132 + c) = make_float2(cc[2], cc[3]);
        }
    }
    __syncthreads();

    // ---- fused epilogue by region ----
    if (n0 < QCOLS) {
        const int head = n0 >> 7;
        const float scale = 0.08838834764831845f;
        for (int it = 0; it < 32; it++) {
            const int idx = tid + it * 256;
            const int r = idx >> 6, i = idx & 63;
            const int grow = m0 + r;
            const int pos = grow & (SEQ - 1);
            const float x1 = ft[r * 132 + i];
            const float x2 = ft[r * 132 + i + 64];
            const float c = g_cos[pos * 64 + i];
            const float s = g_sin[pos * 64 + i];
            const float y1 = (x1 * c - x2 * s) * scale;
            const float y2 = (x2 * c + x1 * s) * scale;
            const size_t o = (size_t)grow * QCOLS + head * HDIM + i;
            Qh[o]      = __float2half_rn(y1);
            Qh[o + 64] = __float2half_rn(y2);
        }
    } else if (n0 < QCOLS + KCOLS) {
        const int head = (n0 - QCOLS) >> 7;
        for (int it = 0; it < 32; it++) {
            const int idx = tid + it * 256;
            const int r = idx >> 6, i = idx & 63;
            const int grow = m0 + r;
            const int pos = grow & (SEQ - 1);
            const float x1 = ft[r * 132 + i];
            const float x2 = ft[r * 132 + i + 64];
            const float c = g_cos[pos * 64 + i];
            const float s = g_sin[pos * 64 + i];
            const float y1 = x1 * c - x2 * s;
            const float y2 = x2 * c + x1 * s;
            const __half h1 = __float2half_rn(y1);
            const __half h2 = __float2half_rn(y2);
            const size_t o = (size_t)grow * KCOLS + head * HDIM + i;
            Kh[o]      = h1;
            Kh[o + 64] = h2;
            Kl[o]      = __float2half_rn(y1 - __half2float(h1));
            Kl[o + 64] = __float2half_rn(y2 - __half2float(h2));
        }
    } else {
        // V head: hi only
        const int cbase = n0 - (QCOLS + KCOLS);
        for (int it = 0; it < 64; it++) {
            const int idx = tid + it * 256;
            const int r = idx >> 7, c = idx & 127;
            const int grow = m0 + r;
            const float x = ft[r * 132 + c];
            Vh[(size_t)grow * KCOLS + cbase + c] = __float2half_rn(x);
        }
    }
}

// ---------------------------------------------------------------------------
// Flash attention (round-11 structure): FKT=64, 2-stage KV double buffer.
// QK^T: Qh*(Kh+Kl) 2-product.  PV: Ph*Vh single product (V hi only).
// Stage = Kh+Kl+Vh = 48KB; smem = 32 + 2*48 = 128KB -> 1 CTA/SM.
// qt descending (heavy tiles first). Writes ctx hi only.
// ---------------------------------------------------------------------------
#define FQT 128
#define FKT 64
#define FQ_B    32768
#define FTILE_B 16384
#define FKV_B   (3*FTILE_B)                 // Kh,Kl,Vh per stage = 48KB
#define FLASH_SMEM (FQ_B + 2*FKV_B)         // 128KB

__global__ __launch_bounds__(256, 1)
void flash_mma(const __half* __restrict__ Qh_g,
               const __half* __restrict__ Kh_g, const __half* __restrict__ Kl_g,
               const __half* __restrict__ Vh_g,
               __half* __restrict__ Ch_g)
{
    extern __shared__ char dsm[];
    const uint32_t sb = smem_u32(dsm);
    const uint32_t Qh_s = sb;
    const uint32_t KV_s = sb + FQ_B;

    const int tid = threadIdx.x;
    const int w = tid >> 5, lane = tid & 31;
    const int qt = gridDim.x - 1 - blockIdx.x;
    const int h = blockIdx.y, b = blockIdx.z;
    const int kvh = h >> 2;
    const int qrow0 = b * SEQ + qt * FQT;
    const int nkt = 2 * qt + 2;

    {
        const int c = tid & 15, r0 = tid >> 4;
        #pragma unroll
        for (int i = 0; i < 8; i++) {
            const int r = r0 + i * 16;
            const size_t go = (size_t)(qrow0 + r) * QCOLS + h * HDIM + c * 8;
            cp_async16(Qh_s + SW(r, c), Qh_g + go);
        }
    }

    auto load_kv = [&](int kt, int st) {
        const int c = tid & 15, r0 = tid >> 4;
        const uint32_t base = KV_s + st * FKV_B;
        const int krow0 = b * SEQ + kt * FKT;
        #pragma unroll
        for (int i = 0; i < 4; i++) {
            const int r = r0 + i * 16;
            const size_t go = (size_t)(krow0 + r) * KCOLS + kvh * HDIM + c * 8;
            cp_async16(base +             SW(r, c), Kh_g + go);
            cp_async16(base +   FTILE_B + SW(r, c), Kl_g + go);
            cp_async16(base + 2*FTILE_B + SW(r, c), Vh_g + go);
        }
        asm volatile("cp.async.commit_group;\n" ::: "memory");
    };

    load_kv(0, 0);
    asm volatile("cp.async.commit_group;\n" ::: "memory");  // empty group (Q rides group 0)

    const int er = lane >> 2, ec = lane & 3;
    const int a_row = w * 16 + (lane & 15);
    const int a_kh  = lane >> 4;
    const int b_n   = (lane & 7) + ((lane >> 4) & 1) * 8;
    const int b_kh  = (lane >> 3) & 1;
    const int v_key = (lane & 7) + ((lane >> 3) & 1) * 8;
    const int v_dc  = lane >> 4;

    const int rg0 = qt * FQT + w * 16 + er;
    const int rg1 = rg0 + 8;

    float o[16][4];
    #pragma unroll
    for (int j = 0; j < 16; j++)
        #pragma unroll
        for (int q = 0; q < 4; q++) o[j][q] = 0.0f;
    float m0 = -1e30f, m1 = -1e30f, l0 = 0.0f, l1 = 0.0f;

    for (int kt = 0; kt < nkt; kt++) {
        const int st = kt & 1;
        if (kt + 1 < nkt) {
            load_kv(kt + 1, (kt + 1) & 1);
            asm volatile("cp.async.wait_group 1;\n" ::: "memory");
        } else {
            asm volatile("cp.async.wait_group 0;\n" ::: "memory");
        }
        __syncthreads();

        const uint32_t Kh_s = KV_s + st * FKV_B;
        const uint32_t Kl_s = Kh_s + FTILE_B;
        const uint32_t Vh_s = Kh_s + 2 * FTILE_B;

        float s[8][4];
        #pragma unroll
        for (int f = 0; f < 8; f++)
            #pragma unroll
            for (int q = 0; q < 4; q++) s[f][q] = 0.0f;

        #pragma unroll
        for (int ks = 0; ks < 8; ks++) {
            uint32_t qa[4];
            ldsm_x4(qa[0], qa[1], qa[2], qa[3], Qh_s + SW(a_row, ks*2 + a_kh));
            #pragma unroll
            for (int ng = 0; ng < 4; ng++) {
                uint32_t kh0, kh1, kh2, kh3, kl0, kl1, kl2, kl3;
                ldsm_x4(kh0, kh1, kh2, kh3, Kh_s + SW(ng*16 + b_n, ks*2 + b_kh));
                ldsm_x4(kl0, kl1, kl2, kl3, Kl_s + SW(ng*16 + b_n, ks*2 + b_kh));
                float* s0 = s[ng*2];
                float* s1 = s[ng*2 + 1];
                mma16816(s0[0], s0[1], s0[2], s0[3], qa[0], qa[1], qa[2], qa[3], kh0, kh1);
                mma16816(s1[0], s1[1], s1[2], s1[3], qa[0], qa[1], qa[2], qa[3], kh2, kh3);
                mma16816(s0[0], s0[1], s0[2], s0[3], qa[0], qa[1], qa[2], qa[3], kl0, kl1);
                mma16816(s1[0], s1[1], s1[2], s1[3], qa[0], qa[1], qa[2], qa[3], kl2, kl3);
            }
        }

        if (kt >= 2 * qt) {
            #pragma unroll
            for (int f = 0; f < 8; f++) {
                const int key0 = kt * FKT + f * 8 + ec * 2;
                if (key0     > rg0) s[f][0] = -1e30f;
                if (key0 + 1 > rg0) s[f][1] = -1e30f;
                if (key0     > rg1) s[f][2] = -1e30f;
                if (key0 + 1 > rg1) s[f][3] = -1e30f;
            }
        }

        float nm0 = -1e30f, nm1 = -1e30f;
        #pragma unroll
        for (int f = 0; f < 8; f++) {
            nm0 = fmaxf(nm0, fmaxf(s[f][0], s[f][1]));
            nm1 = fmaxf(nm1, fmaxf(s[f][2], s[f][3]));
        }
        nm0 = fmaxf(nm0, __shfl_xor_sync(0xffffffffu, nm0, 1));
        nm0 = fmaxf(nm0, __shfl_xor_sync(0xffffffffu, nm0, 2));
        nm1 = fmaxf(nm1, __shfl_xor_sync(0xffffffffu, nm1, 1));
        nm1 = fmaxf(nm1, __shfl_xor_sync(0xffffffffu, nm1, 2));
        nm0 = fmaxf(nm0, m0);
        nm1 = fmaxf(nm1, m1);
        const float corr0 = __expf(m0 - nm0);
        const float corr1 = __expf(m1 - nm1);
        m0 = nm0;
        m1 = nm1;

        float rs0 = 0.0f, rs1 = 0.0f;
        #pragma unroll
        for (int f = 0; f < 8; f++) {
            s[f][0] = __expf(s[f][0] - nm0);
            s[f][1] = __expf(s[f][1] - nm0);
            s[f][2] = __expf(s[f][2] - nm1);
            s[f][3] = __expf(s[f][3] - nm1);
            rs0 += s[f][0] + s[f][1];
            rs1 += s[f][2] + s[f][3];
        }
        rs0 += __shfl_xor_sync(0xffffffffu, rs0, 1);
        rs0 += __shfl_xor_sync(0xffffffffu, rs0, 2);
        rs1 += __shfl_xor_sync(0xffffffffu, rs1, 1);
        rs1 += __shfl_xor_sync(0xffffffffu, rs1, 2);
        l0 = l0 * corr0 + rs0;
        l1 = l1 * corr1 + rs1;
        #pragma unroll
        for (int j = 0; j < 16; j++) {
            o[j][0] *= corr0; o[j][1] *= corr0;
            o[j][2] *= corr1; o[j][3] *= corr1;
        }

        #pragma unroll
        for (int kp = 0; kp < 4; kp++) {
            const float* f0 = s[2*kp];
            const float* f1 = s[2*kp + 1];
            uint32_t pa[4];
            __half2 t;
            t = __floats2half2_rn(f0[0], f0[1]); pa[0] = *reinterpret_cast<uint32_t*>(&t);
            t = __floats2half2_rn(f0[2], f0[3]); pa[1] = *reinterpret_cast<uint32_t*>(&t);
            t = __floats2half2_rn(f1[0], f1[1]); pa[2] = *reinterpret_cast<uint32_t*>(&t);
            t = __floats2half2_rn(f1[2], f1[3]); pa[3] = *reinterpret_cast<uint32_t*>(&t);

            #pragma unroll
            for (int nd = 0; nd < 8; nd++) {
                uint32_t vh0, vh1, vh2, vh3;
                ldsm_x4t(vh0, vh1, vh2, vh3, Vh_s + SW(kp*16 + v_key, nd*2 + v_dc));
                float* o0 = o[nd*2];
                float* o1 = o[nd*2 + 1];
                mma16816(o0[0], o0[1], o0[2], o0[3], pa[0], pa[1], pa[2], pa[3], vh0, vh1);
                mma16816(o1[0], o1[1], o1[2], o1[3], pa[0], pa[1], pa[2], pa[3], vh2, vh3);
            }
        }
        __syncthreads();   // all reads of stage st done
    }

    const float inv0 = 1.0f / l0;
    const float inv1 = 1.0f / l1;
    const size_t row0 = (size_t)(qrow0 + w * 16 + er);
    const size_t row1 = row0 + 8;
    #pragma unroll
    for (int j = 0; j < 16; j++) {
        const int col = h * HDIM + j * 8 + ec * 2;
        *reinterpret_cast<__half2*>(Ch_g + row0 * QCOLS + col) =
            __floats2half2_rn(o[j][0] * inv0, o[j][1] * inv0);
        *reinterpret_cast<__half2*>(Ch_g + row1 * QCOLS + col) =
            __floats2half2_rn(o[j][2] * inv1, o[j][3] * inv1);
    }
}

// ---------------------------------------------------------------------------
extern "C" void kernel_launch(void* const* d_in, const int* in_sizes, int n_in,
                              void* d_out, int out_size)
{
    const float* hidden = (const float*)d_in[0];
    const float* Wq = (const float*)d_in[1];
    const float* Wk = (const float*)d_in[2];
    const float* Wv = (const float*)d_in[3];
    const float* Wo = (const float*)d_in[4];
    float* out = (float*)d_out;

    __half *ah, *ch, *qh, *kh, *kl, *vh, *wh, *wl, *woh, *wol;
    cudaGetSymbolAddress((void**)&ah, g_ah);
    cudaGetSymbolAddress((void**)&ch, g_ch);
    cudaGetSymbolAddress((void**)&qh, g_qh);
    cudaGetSymbolAddress((void**)&kh, g_kh);  cudaGetSymbolAddress((void**)&kl, g_kl);
    cudaGetSymbolAddress((void**)&vh, g_vh);
    cudaGetSymbolAddress((void**)&wh, g_wh);  cudaGetSymbolAddress((void**)&wl, g_wl);
    cudaGetSymbolAddress((void**)&woh, g_woh); cudaGetSymbolAddress((void**)&wol, g_wol);

    cudaFuncSetAttribute(gemm_mma,
                         cudaFuncAttributeMaxDynamicSharedMemorySize, GEMM_SMEM);
    cudaFuncSetAttribute(gemm_qkv_fused,
                         cudaFuncAttributeMaxDynamicSharedMemorySize, GEMM_SMEM);
    cudaFuncSetAttribute(flash_mma,
                         cudaFuncAttributeMaxDynamicSharedMemorySize, FLASH_SMEM);

    // 1) RoPE table, 2) hidden hi-split, 3) all weight transposes (one launch)
    rope_table_kernel<<<(SEQ*64 + 255)/256, 256>>>();
    split_hi_kernel<<<(ROWS*HID/4 + 255)/256, 256>>>(hidden, ah, ROWS*HID/4);
    tsplit_all_kernel<<<10240, dim3(32,8)>>>(Wq, Wk, Wv, Wo, wh, wl, woh, wol);

    // 4) Merged QKV projection with fused RoPE/scale/split epilogue
    gemm_qkv_fused<<<dim3(QKVC/128, ROWS/128), 256, GEMM_SMEM>>>(
        ah, wh, wl, qh, kh, kl, vh);

    // 5) Attention, writes ctx hi directly
    flash_mma<<<dim3(SEQ/FQT, NHQ, BATCH), 256, FLASH_SMEM>>>(qh, kh, kl, vh, ch);

    // 6) Output projection
    gemm_mma<<<dim3(HID/128, ROWS/128), 256, GEMM_SMEM>>>(ch, woh, wol, out, HID);
}

// round 15
// speedup vs baseline: 1.1826x; 1.0560x over previous
#include <cuda_runtime.h>
#include <cuda_fp16.h>
#include <math.h>
#include <stdint.h>

// Problem constants
#define BATCH 2
#define SEQ   2048
#define HID   2048
#define NHQ   16
#define NKV   4
#define HDIM  128
#define ROWS  (BATCH*SEQ)          // 4096
#define QCOLS (NHQ*HDIM)           // 2048
#define KCOLS (NKV*HDIM)           // 512
#define QKVC  (QCOLS + 2*KCOLS)    // 3072

// ---------------------------------------------------------------------------
// Device scratch (static — no allocation allowed)
// ---------------------------------------------------------------------------
__device__ float g_cos[SEQ*64];
__device__ float g_sin[SEQ*64];

__device__ __half g_ah[ROWS*HID];                       // hidden (hi only)
__device__ __half g_ch[ROWS*QCOLS];                     // ctx (hi only)
__device__ __half g_qh[ROWS*QCOLS];                     // q (hi only, rope+scale)
__device__ __half g_kh[ROWS*KCOLS];                     // k hi only (rope)
__device__ __half g_vh[ROWS*KCOLS];                     // v hi only
__device__ __half g_wh[QKVC*HID],   g_wl[QKVC*HID];     // [Wq;Wk;Wv]^T hi/lo
__device__ __half g_woh[HID*QCOLS], g_wol[HID*QCOLS];   // Wo^T hi/lo

// ---------------------------------------------------------------------------
// Helpers
// ---------------------------------------------------------------------------
__device__ __forceinline__ uint32_t smem_u32(const void* p) {
    uint32_t a;
    asm("{ .reg .u64 t; cvta.to.shared.u64 t, %1; cvt.u32.u64 %0, t; }" : "=r"(a) : "l"(p));
    return a;
}
__device__ __forceinline__ void cp_async16(uint32_t dst, const void* src) {
    asm volatile("cp.async.cg.shared.global [%0], [%1], 16;\n" :: "r"(dst), "l"(src) : "memory");
}
__device__ __forceinline__ void ldsm_x4(uint32_t& r0, uint32_t& r1, uint32_t& r2, uint32_t& r3,
                                        uint32_t addr) {
    asm volatile("ldmatrix.sync.aligned.m8n8.x4.shared.b16 {%0,%1,%2,%3}, [%4];"
                 : "=r"(r0), "=r"(r1), "=r"(r2), "=r"(r3) : "r"(addr));
}
__device__ __forceinline__ void ldsm_x4t(uint32_t& r0, uint32_t& r1, uint32_t& r2, uint32_t& r3,
                                         uint32_t addr) {
    asm volatile("ldmatrix.sync.aligned.m8n8.x4.trans.shared.b16 {%0,%1,%2,%3}, [%4];"
                 : "=r"(r0), "=r"(r1), "=r"(r2), "=r"(r3) : "r"(addr));
}
__device__ __forceinline__ void mma16816(float& c0, float& c1, float& c2, float& c3,
                                         uint32_t a0, uint32_t a1, uint32_t a2, uint32_t a3,
                                         uint32_t b0, uint32_t b1) {
    asm volatile(
        "mma.sync.aligned.m16n8k16.row.col.f32.f16.f16.f32 "
        "{%0,%1,%2,%3}, {%4,%5,%6,%7}, {%8,%9}, {%0,%1,%2,%3};"
        : "+f"(c0), "+f"(c1), "+f"(c2), "+f"(c3)
        : "r"(a0), "r"(a1), "r"(a2), "r"(a3), "r"(b0), "r"(b1));
}
// flash smem swizzle: row r (256B rows of fp16[128]), 16B chunk c (0..15)
#define SW(r, c) ((uint32_t)((r) * 256 + (((c) ^ ((r) & 7)) << 4)))
// gemm smem swizzle: row r (128B rows of fp16[64]), 16B chunk c (0..7)
#define SWG(r, c) ((uint32_t)((r) * 128 + (((c) ^ ((r) & 7)) << 4)))

// ---------------------------------------------------------------------------
// fp32 -> fp16 hi (row-major, same layout)
// ---------------------------------------------------------------------------
__global__ void split_hi_kernel(const float* __restrict__ in,
                                __half* __restrict__ hi, int n4)
{
    int i = blockIdx.x * blockDim.x + threadIdx.x;
    if (i >= n4) return;
    float4 v = reinterpret_cast<const float4*>(in)[i];
    __half2* hp = reinterpret_cast<__half2*>(hi);
    hp[2*i]   = __floats2half2_rn(v.x, v.y);
    hp[2*i+1] = __floats2half2_rn(v.z, v.w);
}

// All four weight transposes+splits (fp16 hi/lo) in ONE launch.
__global__ void tsplit_all_kernel(const float* __restrict__ Wq, const float* __restrict__ Wk,
                                  const float* __restrict__ Wv, const float* __restrict__ Wo,
                                  __half* __restrict__ wh, __half* __restrict__ wl,
                                  __half* __restrict__ woh, __half* __restrict__ wol)
{
    __shared__ float t[32][33];
    const int bid = blockIdx.x;
    const float* src;
    __half *dh, *dl;
    int Nin, nbx, tile;
    if (bid < 4096)      { src = Wq; dh = wh; dl = wl; Nin = 2048; nbx = 64; tile = bid; }
    else if (bid < 5120) { src = Wk; dh = wh + (size_t)QCOLS*HID; dl = wl + (size_t)QCOLS*HID;
                           Nin = 512; nbx = 16; tile = bid - 4096; }
    else if (bid < 6144) { src = Wv; dh = wh + (size_t)(QCOLS+KCOLS)*HID; dl = wl + (size_t)(QCOLS+KCOLS)*HID;
                           Nin = 512; nbx = 16; tile = bid - 5120; }
    else                 { src = Wo; dh = woh; dl = wol; Nin = 2048; nbx = 64; tile = bid - 6144; }

    const int tx = threadIdx.x, ty = threadIdx.y;
    const int n0 = (tile % nbx) * 32, k0 = (tile / nbx) * 32;
    #pragma unroll
    for (int j = 0; j < 32; j += 8)
        t[ty + j][tx] = src[(size_t)(k0 + ty + j) * Nin + n0 + tx];
    __syncthreads();
    #pragma unroll
    for (int j = 0; j < 32; j += 8) {
        float x = t[tx][ty + j];
        __half h = __float2half_rn(x);
        __half l = __float2half_rn(x - __half2float(h));
        size_t o = (size_t)(n0 + ty + j) * 2048 + k0 + tx;
        dh[o] = h;
        dl[o] = l;
    }
}

// ---------------------------------------------------------------------------
// RoPE table
// ---------------------------------------------------------------------------
__global__ void rope_table_kernel()
{
    int idx = blockIdx.x * blockDim.x + threadIdx.x;
    if (idx >= SEQ * 64) return;
    int pos = idx >> 6, i = idx & 63;
    double inv = exp2(-(double)i * (13.287712379549449 / 64.0));
    double ang = (double)pos * inv;
    const double twopi = 6.283185307179586476925286766559;
    ang -= floor(ang * (1.0 / twopi)) * twopi;
    if (ang > 3.14159265358979323846) ang -= twopi;
    float s, c;
    sincosf((float)ang, &s, &c);
    g_cos[idx] = c;
    g_sin[idx] = s;
}

// ---------------------------------------------------------------------------
// GEMM mainloop: 128x128 CTA tile, fp16 2-product (Ah*Bh + Ah*Bl).
// KCH=64 (32 chunks), 2-stage double buffer, one sync per chunk, 2 CTAs/SM.
// ---------------------------------------------------------------------------
#define KCH       64
#define NCHUNKS   32
#define TILE_B    16384           // 128 rows x 128 B
#define STAGE_B   (3*TILE_B)      // 48 KB
#define NSTG      2
#define GEMM_SMEM (NSTG*STAGE_B)  // 96 KB

struct GemmCtx {
    uint32_t sbase;
    const __half* gsrc;
    int row0, lch, lr0;
    uint32_t smoff;
    int m0w, n0w;
    int a_row, a_kh, b_row, b_kh;
};

__device__ __forceinline__ void gemm_mainloop(
    const GemmCtx& cx, float acc[4][4][4])
{
    auto load_chunk = [&](int ci, int st) {
        if (cx.gsrc) {
            const uint32_t tb = cx.sbase + st * STAGE_B + cx.smoff;
            #pragma unroll
            for (int i = 0; i < 16; i++) {
                const int r = cx.lr0 + i * 8;
                const uint32_t dst = tb + SWG(r, cx.lch);
                cp_async16(dst, cx.gsrc + (size_t)(cx.row0 + r) * 2048 + ci * KCH + cx.lch * 8);
            }
        }
        asm volatile("cp.async.commit_group;\n" ::: "memory");
    };

    load_chunk(0, 0);

    for (int ci = 0; ci < NCHUNKS; ci++) {
        asm volatile("cp.async.wait_group 0;\n" ::: "memory");
        __syncthreads();
        if (ci + 1 < NCHUNKS) load_chunk(ci + 1, (ci + 1) & 1);

        const uint32_t ah_b = cx.sbase + (ci & 1) * STAGE_B;
        const uint32_t bh_b = ah_b + TILE_B;
        const uint32_t bl_b = ah_b + 2 * TILE_B;

        #pragma unroll
        for (int ks = 0; ks < 4; ks++) {
            uint32_t a4[4][4];
            #pragma unroll
            for (int mi = 0; mi < 4; mi++) {
                const int r = cx.m0w + mi * 16 + cx.a_row;
                ldsm_x4(a4[mi][0], a4[mi][1], a4[mi][2], a4[mi][3],
                        ah_b + SWG(r, ks * 2 + cx.a_kh));
            }
            uint32_t bh[4][2], bl[4][2];
            #pragma unroll
            for (int jb = 0; jb < 2; jb++) {
                const int r = cx.n0w + jb * 16 + cx.b_row;
                const uint32_t off = SWG(r, ks * 2 + cx.b_kh);
                ldsm_x4(bh[2*jb][0], bh[2*jb][1], bh[2*jb+1][0], bh[2*jb+1][1], bh_b + off);
                ldsm_x4(bl[2*jb][0], bl[2*jb][1], bl[2*jb+1][0], bl[2*jb+1][1], bl_b + off);
            }
            #pragma unroll
            for (int mi = 0; mi < 4; mi++)
                #pragma unroll
                for (int nj = 0; nj < 4; nj++) {
                    float* cc = acc[mi][nj];
                    mma16816(cc[0], cc[1], cc[2], cc[3],
                             a4[mi][0], a4[mi][1], a4[mi][2], a4[mi][3],
                             bh[nj][0], bh[nj][1]);
                }
            #pragma unroll
            for (int mi = 0; mi < 4; mi++)
                #pragma unroll
                for (int nj = 0; nj < 4; nj++) {
                    float* cc = acc[mi][nj];
                    mma16816(cc[0], cc[1], cc[2], cc[3],
                             a4[mi][0], a4[mi][1], a4[mi][2], a4[mi][3],
                             bl[nj][0], bl[nj][1]);
                }
        }
    }
}

__device__ __forceinline__ void gemm_init_ctx(
    GemmCtx& cx, uint32_t sbase, int tid, int m0, int n0,
    const __half* Ah, const __half* Bh, const __half* Bl)
{
    cx.sbase = sbase;
    const int tt = tid >> 6;
    const int t6 = tid & 63;
    cx.lch = t6 & 7;
    cx.lr0 = t6 >> 3;
    switch (tt) {
        case 0:  cx.gsrc = Ah; cx.row0 = m0; cx.smoff = 0;          break;
        case 1:  cx.gsrc = Bh; cx.row0 = n0; cx.smoff = TILE_B;     break;
        case 2:  cx.gsrc = Bl; cx.row0 = n0; cx.smoff = 2*TILE_B;   break;
        default: cx.gsrc = nullptr; cx.row0 = 0; cx.smoff = 0;      break;
    }
    const int wid = tid >> 5, lane = tid & 31;
    cx.m0w = (wid & 1) * 64;
    cx.n0w = (wid >> 1) * 32;
    cx.a_row = lane & 15;
    cx.a_kh  = lane >> 4;
    cx.b_row = (lane & 7) + ((lane >> 4) & 1) * 8;
    cx.b_kh  = (lane >> 3) & 1;
}

// ---------------------------------------------------------------------------
// Plain GEMM (fp32 C output) — output projection.
// ---------------------------------------------------------------------------
__global__ __launch_bounds__(256, 2)
void gemm_mma(const __half* __restrict__ Ah,
              const __half* __restrict__ Bh, const __half* __restrict__ Bl,
              float* __restrict__ C, int ldc)
{
    extern __shared__ char dsm[];
    const int tid = threadIdx.x;
    const int lane = tid & 31;
    const int m0 = blockIdx.y * 128;
    const int n0 = blockIdx.x * 128;

    GemmCtx cx;
    gemm_init_ctx(cx, smem_u32(dsm), tid, m0, n0, Ah, Bh, Bl);

    float acc[4][4][4];
    #pragma unroll
    for (int i = 0; i < 4; i++)
        #pragma unroll
        for (int j = 0; j < 4; j++)
            #pragma unroll
            for (int q = 0; q < 4; q++) acc[i][j][q] = 0.0f;

    gemm_mainloop(cx, acc);

    const int er = lane >> 2;
    const int ec = (lane & 3) * 2;
    #pragma unroll
    for (int mi = 0; mi < 4; mi++) {
        const int row_a = m0 + cx.m0w + mi * 16 + er;
        #pragma unroll
        for (int nj = 0; nj < 4; nj++) {
            const int col = n0 + cx.n0w + nj * 8 + ec;
            float* cc = acc[mi][nj];
            *reinterpret_cast<float2*>(C + (size_t)row_a * ldc + col) =
                make_float2(cc[0], cc[1]);
            *reinterpret_cast<float2*>(C + (size_t)(row_a + 8) * ldc + col) =
                make_float2(cc[2], cc[3]);
        }
    }
}

// ---------------------------------------------------------------------------
// QKV GEMM with fused RoPE + scale + fp16 epilogue.
// Q: hi only (+scale).  K: hi only (rope).  V: hi only.
// ---------------------------------------------------------------------------
__global__ __launch_bounds__(256, 2)
void gemm_qkv_fused(const __half* __restrict__ Ah,
                    const __half* __restrict__ Bh, const __half* __restrict__ Bl,
                    __half* __restrict__ Qh,
                    __half* __restrict__ Kh,
                    __half* __restrict__ Vh)
{
    extern __shared__ char dsm[];
    const int tid = threadIdx.x;
    const int lane = tid & 31;
    const int m0 = blockIdx.y * 128;
    const int n0 = blockIdx.x * 128;

    GemmCtx cx;
    gemm_init_ctx(cx, smem_u32(dsm), tid, m0, n0, Ah, Bh, Bl);

    float acc[4][4][4];
    #pragma unroll
    for (int i = 0; i < 4; i++)
        #pragma unroll
        for (int j = 0; j < 4; j++)
            #pragma unroll
            for (int q = 0; q < 4; q++) acc[i][j][q] = 0.0f;

    gemm_mainloop(cx, acc);

    // ---- stage fp32 tile to smem [128][132] ----
    __syncthreads();
    float* ft = reinterpret_cast<float*>(dsm);
    const int er = lane >> 2;
    const int ec = (lane & 3) * 2;
    #pragma unroll
    for (int mi = 0; mi < 4; mi++) {
        const int r = cx.m0w + mi * 16 + er;
        #pragma unroll
        for (int nj = 0; nj < 4; nj++) {
            const int c = cx.n0w + nj * 8 + ec;
            float* cc = acc[mi][nj];
            *reinterpret_cast<float2*>(ft + r * 132 + c)       = make_float2(cc[0], cc[1]);
            *reinterpret_cast<float2*>(ft + (r + 8) * 132 + c) = make_float2(cc[2], cc[3]);
        }
    }
    __syncthreads();

    // ---- fused epilogue by region ----
    if (n0 < QCOLS) {
        const int head = n0 >> 7;
        const float scale = 0.08838834764831845f;
        for (int it = 0; it < 32; it++) {
            const int idx = tid + it * 256;
            const int r = idx >> 6, i = idx & 63;
            const int grow = m0 + r;
            const int pos = grow & (SEQ - 1);
            const float x1 = ft[r * 132 + i];
            const float x2 = ft[r * 132 + i + 64];
            const float c = g_cos[pos * 64 + i];
            const float s = g_sin[pos * 64 + i];
            const float y1 = (x1 * c - x2 * s) * scale;
            const float y2 = (x2 * c + x1 * s) * scale;
            const size_t o = (size_t)grow * QCOLS + head * HDIM + i;
            Qh[o]      = __float2half_rn(y1);
            Qh[o + 64] = __float2half_rn(y2);
        }
    } else if (n0 < QCOLS + KCOLS) {
        const int head = (n0 - QCOLS) >> 7;
        for (int it = 0; it < 32; it++) {
            const int idx = tid + it * 256;
            const int r = idx >> 6, i = idx & 63;
            const int grow = m0 + r;
            const int pos = grow & (SEQ - 1);
            const float x1 = ft[r * 132 + i];
            const float x2 = ft[r * 132 + i + 64];
            const float c = g_cos[pos * 64 + i];
            const float s = g_sin[pos * 64 + i];
            const float y1 = x1 * c - x2 * s;
            const float y2 = x2 * c + x1 * s;
            const size_t o = (size_t)grow * KCOLS + head * HDIM + i;
            Kh[o]      = __float2half_rn(y1);
            Kh[o + 64] = __float2half_rn(y2);
        }
    } else {
        const int cbase = n0 - (QCOLS + KCOLS);
        for (int it = 0; it < 64; it++) {
            const int idx = tid + it * 256;
            const int r = idx >> 7, c = idx & 127;
            const int grow = m0 + r;
            const float x = ft[r * 132 + c];
            Vh[(size_t)grow * KCOLS + cbase + c] = __float2half_rn(x);
        }
    }
}

// ---------------------------------------------------------------------------
// Flash attention: pure fp16 single-product (Qh*Kh; Ph*Vh).
// FKT=64, 2-stage KV double buffer (Kh+Vh = 32KB/stage).
// Smem = 32 + 2*32 = 96KB -> 2 CTAs/SM with the proven prefetch schedule.
// qt descending (heavy tiles first). Writes ctx hi only.
// ---------------------------------------------------------------------------
#define FQT 128
#define FKT 64
#define FQ_B    32768
#define FTILE_B 16384
#define FKV_B   (2*FTILE_B)                 // Kh,Vh per stage = 32KB
#define FLASH_SMEM (FQ_B + 2*FKV_B)         // 96KB

__global__ __launch_bounds__(256, 2)
void flash_mma(const __half* __restrict__ Qh_g,
               const __half* __restrict__ Kh_g,
               const __half* __restrict__ Vh_g,
               __half* __restrict__ Ch_g)
{
    extern __shared__ char dsm[];
    const uint32_t sb = smem_u32(dsm);
    const uint32_t Qh_s = sb;
    const uint32_t KV_s = sb + FQ_B;

    const int tid = threadIdx.x;
    const int w = tid >> 5, lane = tid & 31;
    const int qt = gridDim.x - 1 - blockIdx.x;
    const int h = blockIdx.y, b = blockIdx.z;
    const int kvh = h >> 2;
    const int qrow0 = b * SEQ + qt * FQT;
    const int nkt = 2 * qt + 2;

    {
        const int c = tid & 15, r0 = tid >> 4;
        #pragma unroll
        for (int i = 0; i < 8; i++) {
            const int r = r0 + i * 16;
            const size_t go = (size_t)(qrow0 + r) * QCOLS + h * HDIM + c * 8;
            cp_async16(Qh_s + SW(r, c), Qh_g + go);
        }
    }

    auto load_kv = [&](int kt, int st) {
        const int c = tid & 15, r0 = tid >> 4;
        const uint32_t base = KV_s + st * FKV_B;
        const int krow0 = b * SEQ + kt * FKT;
        #pragma unroll
        for (int i = 0; i < 4; i++) {
            const int r = r0 + i * 16;
            const size_t go = (size_t)(krow0 + r) * KCOLS + kvh * HDIM + c * 8;
            cp_async16(base +           SW(r, c), Kh_g + go);
            cp_async16(base + FTILE_B + SW(r, c), Vh_g + go);
        }
        asm volatile("cp.async.commit_group;\n" ::: "memory");
    };

    load_kv(0, 0);
    asm volatile("cp.async.commit_group;\n" ::: "memory");  // empty group (Q rides group 0)

    const int er = lane >> 2, ec = lane & 3;
    const int a_row = w * 16 + (lane & 15);
    const int a_kh  = lane >> 4;
    const int b_n   = (lane & 7) + ((lane >> 4) & 1) * 8;
    const int b_kh  = (lane >> 3) & 1;
    const int v_key = (lane & 7) + ((lane >> 3) & 1) * 8;
    const int v_dc  = lane >> 4;

    const int rg0 = qt * FQT + w * 16 + er;
    const int rg1 = rg0 + 8;

    float o[16][4];
    #pragma unroll
    for (int j = 0; j < 16; j++)
        #pragma unroll
        for (int q = 0; q < 4; q++) o[j][q] = 0.0f;
    float m0 = -1e30f, m1 = -1e30f, l0 = 0.0f, l1 = 0.0f;

    for (int kt = 0; kt < nkt; kt++) {
        const int st = kt & 1;
        if (kt + 1 < nkt) {
            load_kv(kt + 1, (kt + 1) & 1);
            asm volatile("cp.async.wait_group 1;\n" ::: "memory");
        } else {
            asm volatile("cp.async.wait_group 0;\n" ::: "memory");
        }
        __syncthreads();

        const uint32_t Kh_s = KV_s + st * FKV_B;
        const uint32_t Vh_s = Kh_s + FTILE_B;

        float s[8][4];
        #pragma unroll
        for (int f = 0; f < 8; f++)
            #pragma unroll
            for (int q = 0; q < 4; q++) s[f][q] = 0.0f;

        #pragma unroll
        for (int ks = 0; ks < 8; ks++) {
            uint32_t qa[4];
            ldsm_x4(qa[0], qa[1], qa[2], qa[3], Qh_s + SW(a_row, ks*2 + a_kh));
            #pragma unroll
            for (int ng = 0; ng < 4; ng++) {
                uint32_t kh0, kh1, kh2, kh3;
                ldsm_x4(kh0, kh1, kh2, kh3, Kh_s + SW(ng*16 + b_n, ks*2 + b_kh));
                float* s0 = s[ng*2];
                float* s1 = s[ng*2 + 1];
                mma16816(s0[0], s0[1], s0[2], s0[3], qa[0], qa[1], qa[2], qa[3], kh0, kh1);
                mma16816(s1[0], s1[1], s1[2], s1[3], qa[0], qa[1], qa[2], qa[3], kh2, kh3);
            }
        }

        if (kt >= 2 * qt) {
            #pragma unroll
            for (int f = 0; f < 8; f++) {
                const int key0 = kt * FKT + f * 8 + ec * 2;
                if (key0     > rg0) s[f][0] = -1e30f;
                if (key0 + 1 > rg0) s[f][1] = -1e30f;
                if (key0     > rg1) s[f][2] = -1e30f;
                if (key0 + 1 > rg1) s[f][3] = -1e30f;
            }
        }

        float nm0 = -1e30f, nm1 = -1e30f;
        #pragma unroll
        for (int f = 0; f < 8; f++) {
            nm0 = fmaxf(nm0, fmaxf(s[f][0], s[f][1]));
            nm1 = fmaxf(nm1, fmaxf(s[f][2], s[f][3]));
        }
        nm0 = fmaxf(nm0, __shfl_xor_sync(0xffffffffu, nm0, 1));
        nm0 = fmaxf(nm0, __shfl_xor_sync(0xffffffffu, nm0, 2));
        nm1 = fmaxf(nm1, __shfl_xor_sync(0xffffffffu, nm1, 1));
        nm1 = fmaxf(nm1, __shfl_xor_sync(0xffffffffu, nm1, 2));
        nm0 = fmaxf(nm0, m0);
        nm1 = fmaxf(nm1, m1);
        const float corr0 = __expf(m0 - nm0);
        const float corr1 = __expf(m1 - nm1);
        m0 = nm0;
        m1 = nm1;

        float rs0 = 0.0f, rs1 = 0.0f;
        #pragma unroll
        for (int f = 0; f < 8; f++) {
            s[f][0] = __expf(s[f][0] - nm0);
            s[f][1] = __expf(s[f][1] - nm0);
            s[f][2] = __expf(s[f][2] - nm1);
            s[f][3] = __expf(s[f][3] - nm1);
            rs0 += s[f][0] + s[f][1];
            rs1 += s[f][2] + s[f][3];
        }
        rs0 += __shfl_xor_sync(0xffffffffu, rs0, 1);
        rs0 += __shfl_xor_sync(0xffffffffu, rs0, 2);
        rs1 += __shfl_xor_sync(0xffffffffu, rs1, 1);
        rs1 += __shfl_xor_sync(0xffffffffu, rs1, 2);
        l0 = l0 * corr0 + rs0;
        l1 = l1 * corr1 + rs1;
        #pragma unroll
        for (int j = 0; j < 16; j++) {
            o[j][0] *= corr0; o[j][1] *= corr0;
            o[j][2] *= corr1; o[j][3] *= corr1;
        }

        #pragma unroll
        for (int kp = 0; kp < 4; kp++) {
            const float* f0 = s[2*kp];
            const float* f1 = s[2*kp + 1];
            uint32_t pa[4];
            __half2 t;
            t = __floats2half2_rn(f0[0], f0[1]); pa[0] = *reinterpret_cast<uint32_t*>(&t);
            t = __floats2half2_rn(f0[2], f0[3]); pa[1] = *reinterpret_cast<uint32_t*>(&t);
            t = __floats2half2_rn(f1[0], f1[1]); pa[2] = *reinterpret_cast<uint32_t*>(&t);
            t = __floats2half2_rn(f1[2], f1[3]); pa[3] = *reinterpret_cast<uint32_t*>(&t);

            #pragma unroll
            for (int nd = 0; nd < 8; nd++) {
                uint32_t vh0, vh1, vh2, vh3;
                ldsm_x4t(vh0, vh1, vh2, vh3, Vh_s + SW(kp*16 + v_key, nd*2 + v_dc));
                float* o0 = o[nd*2];
                float* o1 = o[nd*2 + 1];
                mma16816(o0[0], o0[1], o0[2], o0[3], pa[0], pa[1], pa[2], pa[3], vh0, vh1);
                mma16816(o1[0], o1[1], o1[2], o1[3], pa[0], pa[1], pa[2], pa[3], vh2, vh3);
            }
        }
        __syncthreads();   // all reads of stage st done
    }

    const float inv0 = 1.0f / l0;
    const float inv1 = 1.0f / l1;
    const size_t row0 = (size_t)(qrow0 + w * 16 + er);
    const size_t row1 = row0 + 8;
    #pragma unroll
    for (int j = 0; j < 16; j++) {
        const int col = h * HDIM + j * 8 + ec * 2;
        *reinterpret_cast<__half2*>(Ch_g + row0 * QCOLS + col) =
            __floats2half2_rn(o[j][0] * inv0, o[j][1] * inv0);
        *reinterpret_cast<__half2*>(Ch_g + row1 * QCOLS + col) =
            __floats2half2_rn(o[j][2] * inv1, o[j][3] * inv1);
    }
}

// ---------------------------------------------------------------------------
extern "C" void kernel_launch(void* const* d_in, const int* in_sizes, int n_in,
                              void* d_out, int out_size)
{
    const float* hidden = (const float*)d_in[0];
    const float* Wq = (const float*)d_in[1];
    const float* Wk = (const float*)d_in[2];
    const float* Wv = (const float*)d_in[3];
    const float* Wo = (const float*)d_in[4];
    float* out = (float*)d_out;

    __half *ah, *ch, *qh, *kh, *vh, *wh, *wl, *woh, *wol;
    cudaGetSymbolAddress((void**)&ah, g_ah);
    cudaGetSymbolAddress((void**)&ch, g_ch);
    cudaGetSymbolAddress((void**)&qh, g_qh);
    cudaGetSymbolAddress((void**)&kh, g_kh);
    cudaGetSymbolAddress((void**)&vh, g_vh);
    cudaGetSymbolAddress((void**)&wh, g_wh);  cudaGetSymbolAddress((void**)&wl, g_wl);
    cudaGetSymbolAddress((void**)&woh, g_woh); cudaGetSymbolAddress((void**)&wol, g_wol);

    cudaFuncSetAttribute(gemm_mma,
                         cudaFuncAttributeMaxDynamicSharedMemorySize, GEMM_SMEM);
    cudaFuncSetAttribute(gemm_qkv_fused,
                         cudaFuncAttributeMaxDynamicSharedMemorySize, GEMM_SMEM);
    cudaFuncSetAttribute(flash_mma,
                         cudaFuncAttributeMaxDynamicSharedMemorySize, FLASH_SMEM);

    // 1) RoPE table, 2) hidden hi-split, 3) all weight transposes (one launch)
    rope_table_kernel<<<(SEQ*64 + 255)/256, 256>>>();
    split_hi_kernel<<<(ROWS*HID/4 + 255)/256, 256>>>(hidden, ah, ROWS*HID/4);
    tsplit_all_kernel<<<10240, dim3(32,8)>>>(Wq, Wk, Wv, Wo, wh, wl, woh, wol);

    // 4) Merged QKV projection with fused RoPE/scale epilogue (all fp16 hi)
    gemm_qkv_fused<<<dim3(QKVC/128, ROWS/128), 256, GEMM_SMEM>>>(
        ah, wh, wl, qh, kh, vh);

    // 5) Attention (pure fp16), writes ctx hi directly
    flash_mma<<<dim3(SEQ/FQT, NHQ, BATCH), 256, FLASH_SMEM>>>(qh, kh, vh, ch);

    // 6) Output projection
    gemm_mma<<<dim3(HID/128, ROWS/128), 256, GEMM_SMEM>>>(ch, woh, wol, out, HID);
}

// round 16
// speedup vs baseline: 1.4501x; 1.2262x over previous
#include <cuda_runtime.h>
#include <cuda_fp16.h>
#include <math.h>
#include <stdint.h>

// Problem constants
#define BATCH 2
#define SEQ   2048
#define HID   2048
#define NHQ   16
#define NKV   4
#define HDIM  128
#define ROWS  (BATCH*SEQ)          // 4096
#define QCOLS (NHQ*HDIM)           // 2048
#define KCOLS (NKV*HDIM)           // 512
#define QKVC  (QCOLS + 2*KCOLS)    // 3072

// ---------------------------------------------------------------------------
// Device scratch (static — no allocation allowed)
// ---------------------------------------------------------------------------
__device__ float g_cos[SEQ*64];
__device__ float g_sin[SEQ*64];

__device__ __half g_ah[ROWS*HID];                       // hidden (hi only)
__device__ __half g_ch[ROWS*QCOLS];                     // ctx (hi only)
__device__ __half g_qh[ROWS*QCOLS];                     // q (hi only, rope+scale)
__device__ __half g_kh[ROWS*KCOLS];                     // k hi only (rope)
__device__ __half g_vh[ROWS*KCOLS];                     // v hi only
__device__ __half g_wh[QKVC*HID];                       // [Wq;Wk;Wv]^T hi only
__device__ __half g_woh[HID*QCOLS], g_wol[HID*QCOLS];   // Wo^T hi/lo

// ---------------------------------------------------------------------------
// Helpers
// ---------------------------------------------------------------------------
__device__ __forceinline__ uint32_t smem_u32(const void* p) {
    uint32_t a;
    asm("{ .reg .u64 t; cvta.to.shared.u64 t, %1; cvt.u32.u64 %0, t; }" : "=r"(a) : "l"(p));
    return a;
}
__device__ __forceinline__ void cp_async16(uint32_t dst, const void* src) {
    asm volatile("cp.async.cg.shared.global [%0], [%1], 16;\n" :: "r"(dst), "l"(src) : "memory");
}
__device__ __forceinline__ void ldsm_x4(uint32_t& r0, uint32_t& r1, uint32_t& r2, uint32_t& r3,
                                        uint32_t addr) {
    asm volatile("ldmatrix.sync.aligned.m8n8.x4.shared.b16 {%0,%1,%2,%3}, [%4];"
                 : "=r"(r0), "=r"(r1), "=r"(r2), "=r"(r3) : "r"(addr));
}
__device__ __forceinline__ void ldsm_x4t(uint32_t& r0, uint32_t& r1, uint32_t& r2, uint32_t& r3,
                                         uint32_t addr) {
    asm volatile("ldmatrix.sync.aligned.m8n8.x4.trans.shared.b16 {%0,%1,%2,%3}, [%4];"
                 : "=r"(r0), "=r"(r1), "=r"(r2), "=r"(r3) : "r"(addr));
}
__device__ __forceinline__ void mma16816(float& c0, float& c1, float& c2, float& c3,
                                         uint32_t a0, uint32_t a1, uint32_t a2, uint32_t a3,
                                         uint32_t b0, uint32_t b1) {
    asm volatile(
        "mma.sync.aligned.m16n8k16.row.col.f32.f16.f16.f32 "
        "{%0,%1,%2,%3}, {%4,%5,%6,%7}, {%8,%9}, {%0,%1,%2,%3};"
        : "+f"(c0), "+f"(c1), "+f"(c2), "+f"(c3)
        : "r"(a0), "r"(a1), "r"(a2), "r"(a3), "r"(b0), "r"(b1));
}
// flash smem swizzle: row r (256B rows of fp16[128]), 16B chunk c (0..15)
#define SW(r, c) ((uint32_t)((r) * 256 + (((c) ^ ((r) & 7)) << 4)))
// gemm smem swizzle: row r (128B rows of fp16[64]), 16B chunk c (0..7)
#define SWG(r, c) ((uint32_t)((r) * 128 + (((c) ^ ((r) & 7)) << 4)))

// ---------------------------------------------------------------------------
// fp32 -> fp16 hi (row-major, same layout)
// ---------------------------------------------------------------------------
__global__ void split_hi_kernel(const float* __restrict__ in,
                                __half* __restrict__ hi, int n4)
{
    int i = blockIdx.x * blockDim.x + threadIdx.x;
    if (i >= n4) return;
    float4 v = reinterpret_cast<const float4*>(in)[i];
    __half2* hp = reinterpret_cast<__half2*>(hi);
    hp[2*i]   = __floats2half2_rn(v.x, v.y);
    hp[2*i+1] = __floats2half2_rn(v.z, v.w);
}

// Weight transposes in ONE launch. QKV weights: hi only. Wo: hi+lo.
__global__ void tsplit_all_kernel(const float* __restrict__ Wq, const float* __restrict__ Wk,
                                  const float* __restrict__ Wv, const float* __restrict__ Wo,
                                  __half* __restrict__ wh,
                                  __half* __restrict__ woh, __half* __restrict__ wol)
{
    __shared__ float t[32][33];
    const int bid = blockIdx.x;
    const float* src;
    __half *dh, *dl;
    int Nin, nbx, tile;
    if (bid < 4096)      { src = Wq; dh = wh; dl = nullptr; Nin = 2048; nbx = 64; tile = bid; }
    else if (bid < 5120) { src = Wk; dh = wh + (size_t)QCOLS*HID; dl = nullptr;
                           Nin = 512; nbx = 16; tile = bid - 4096; }
    else if (bid < 6144) { src = Wv; dh = wh + (size_t)(QCOLS+KCOLS)*HID; dl = nullptr;
                           Nin = 512; nbx = 16; tile = bid - 5120; }
    else                 { src = Wo; dh = woh; dl = wol; Nin = 2048; nbx = 64; tile = bid - 6144; }

    const int tx = threadIdx.x, ty = threadIdx.y;
    const int n0 = (tile % nbx) * 32, k0 = (tile / nbx) * 32;
    #pragma unroll
    for (int j = 0; j < 32; j += 8)
        t[ty + j][tx] = src[(size_t)(k0 + ty + j) * Nin + n0 + tx];
    __syncthreads();
    #pragma unroll
    for (int j = 0; j < 32; j += 8) {
        float x = t[tx][ty + j];
        __half h = __float2half_rn(x);
        size_t o = (size_t)(n0 + ty + j) * 2048 + k0 + tx;
        dh[o] = h;
        if (dl) dl[o] = __float2half_rn(x - __half2float(h));
    }
}

// ---------------------------------------------------------------------------
// RoPE table
// ---------------------------------------------------------------------------
__global__ void rope_table_kernel()
{
    int idx = blockIdx.x * blockDim.x + threadIdx.x;
    if (idx >= SEQ * 64) return;
    int pos = idx >> 6, i = idx & 63;
    double inv = exp2(-(double)i * (13.287712379549449 / 64.0));
    double ang = (double)pos * inv;
    const double twopi = 6.283185307179586476925286766559;
    ang -= floor(ang * (1.0 / twopi)) * twopi;
    if (ang > 3.14159265358979323846) ang -= twopi;
    float s, c;
    sincosf((float)ang, &s, &c);
    g_cos[idx] = c;
    g_sin[idx] = s;
}

// ---------------------------------------------------------------------------
// Common GEMM geometry
// ---------------------------------------------------------------------------
#define KCH       64
#define NCHUNKS   32
#define TILE_B    16384           // 128 rows x 128 B

// 2-product variant (out-proj): stage = Ah+Bh+Bl = 48KB, 2 stages = 96KB
#define STAGE2_B  (3*TILE_B)
#define GEMM2_SMEM (2*STAGE2_B)
// 1-product variant (QKV): stage = Ah+Bh = 32KB, 2 stages = 64KB
#define STAGE1_B  (2*TILE_B)
#define GEMM1_SMEM 69632          // 68KB: covers fp32 epilogue tile (67.6KB)

struct GemmCtx {
    uint32_t sbase;
    const __half* gsrc;
    int row0, lch, lr0;
    uint32_t smoff;
    int m0w, n0w;
    int a_row, a_kh, b_row, b_kh;
};

__device__ __forceinline__ void gemm_lane_init(GemmCtx& cx, int tid)
{
    const int wid = tid >> 5, lane = tid & 31;
    cx.m0w = (wid & 1) * 64;
    cx.n0w = (wid >> 1) * 32;
    cx.a_row = lane & 15;
    cx.a_kh  = lane >> 4;
    cx.b_row = (lane & 7) + ((lane >> 4) & 1) * 8;
    cx.b_kh  = (lane >> 3) & 1;
    const int t6 = tid & 63;
    cx.lch = t6 & 7;
    cx.lr0 = t6 >> 3;
}

// ---- 2-product mainloop (Ah*Bh + Ah*Bl) ----
__device__ __forceinline__ void gemm_mainloop2(
    const GemmCtx& cx, float acc[4][4][4])
{
    auto load_chunk = [&](int ci, int st) {
        if (cx.gsrc) {
            const uint32_t tb = cx.sbase + st * STAGE2_B + cx.smoff;
            #pragma unroll
            for (int i = 0; i < 16; i++) {
                const int r = cx.lr0 + i * 8;
                cp_async16(tb + SWG(r, cx.lch),
                           cx.gsrc + (size_t)(cx.row0 + r) * 2048 + ci * KCH + cx.lch * 8);
            }
        }
        asm volatile("cp.async.commit_group;\n" ::: "memory");
    };

    load_chunk(0, 0);

    for (int ci = 0; ci < NCHUNKS; ci++) {
        asm volatile("cp.async.wait_group 0;\n" ::: "memory");
        __syncthreads();
        if (ci + 1 < NCHUNKS) load_chunk(ci + 1, (ci + 1) & 1);

        const uint32_t ah_b = cx.sbase + (ci & 1) * STAGE2_B;
        const uint32_t bh_b = ah_b + TILE_B;
        const uint32_t bl_b = ah_b + 2 * TILE_B;

        #pragma unroll
        for (int ks = 0; ks < 4; ks++) {
            uint32_t a4[4][4];
            #pragma unroll
            for (int mi = 0; mi < 4; mi++) {
                const int r = cx.m0w + mi * 16 + cx.a_row;
                ldsm_x4(a4[mi][0], a4[mi][1], a4[mi][2], a4[mi][3],
                        ah_b + SWG(r, ks * 2 + cx.a_kh));
            }
            uint32_t bh[4][2], bl[4][2];
            #pragma unroll
            for (int jb = 0; jb < 2; jb++) {
                const int r = cx.n0w + jb * 16 + cx.b_row;
                const uint32_t off = SWG(r, ks * 2 + cx.b_kh);
                ldsm_x4(bh[2*jb][0], bh[2*jb][1], bh[2*jb+1][0], bh[2*jb+1][1], bh_b + off);
                ldsm_x4(bl[2*jb][0], bl[2*jb][1], bl[2*jb+1][0], bl[2*jb+1][1], bl_b + off);
            }
            #pragma unroll
            for (int mi = 0; mi < 4; mi++)
                #pragma unroll
                for (int nj = 0; nj < 4; nj++) {
                    float* cc = acc[mi][nj];
                    mma16816(cc[0], cc[1], cc[2], cc[3],
                             a4[mi][0], a4[mi][1], a4[mi][2], a4[mi][3],
                             bh[nj][0], bh[nj][1]);
                }
            #pragma unroll
            for (int mi = 0; mi < 4; mi++)
                #pragma unroll
                for (int nj = 0; nj < 4; nj++) {
                    float* cc = acc[mi][nj];
                    mma16816(cc[0], cc[1], cc[2], cc[3],
                             a4[mi][0], a4[mi][1], a4[mi][2], a4[mi][3],
                             bl[nj][0], bl[nj][1]);
                }
        }
    }
}

// ---- 1-product mainloop (Ah*Bh) ----
__device__ __forceinline__ void gemm_mainloop1(
    const GemmCtx& cx, float acc[4][4][4])
{
    auto load_chunk = [&](int ci, int st) {
        if (cx.gsrc) {
            const uint32_t tb = cx.sbase + st * STAGE1_B + cx.smoff;
            #pragma unroll
            for (int i = 0; i < 16; i++) {
                const int r = cx.lr0 + i * 8;
                cp_async16(tb + SWG(r, cx.lch),
                           cx.gsrc + (size_t)(cx.row0 + r) * 2048 + ci * KCH + cx.lch * 8);
            }
        }
        asm volatile("cp.async.commit_group;\n" ::: "memory");
    };

    load_chunk(0, 0);

    for (int ci = 0; ci < NCHUNKS; ci++) {
        asm volatile("cp.async.wait_group 0;\n" ::: "memory");
        __syncthreads();
        if (ci + 1 < NCHUNKS) load_chunk(ci + 1, (ci + 1) & 1);

        const uint32_t ah_b = cx.sbase + (ci & 1) * STAGE1_B;
        const uint32_t bh_b = ah_b + TILE_B;

        #pragma unroll
        for (int ks = 0; ks < 4; ks++) {
            uint32_t a4[4][4];
            #pragma unroll
            for (int mi = 0; mi < 4; mi++) {
                const int r = cx.m0w + mi * 16 + cx.a_row;
                ldsm_x4(a4[mi][0], a4[mi][1], a4[mi][2], a4[mi][3],
                        ah_b + SWG(r, ks * 2 + cx.a_kh));
            }
            uint32_t bh[4][2];
            #pragma unroll
            for (int jb = 0; jb < 2; jb++) {
                const int r = cx.n0w + jb * 16 + cx.b_row;
                const uint32_t off = SWG(r, ks * 2 + cx.b_kh);
                ldsm_x4(bh[2*jb][0], bh[2*jb][1], bh[2*jb+1][0], bh[2*jb+1][1], bh_b + off);
            }
            #pragma unroll
            for (int mi = 0; mi < 4; mi++)
                #pragma unroll
                for (int nj = 0; nj < 4; nj++) {
                    float* cc = acc[mi][nj];
                    mma16816(cc[0], cc[1], cc[2], cc[3],
                             a4[mi][0], a4[mi][1], a4[mi][2], a4[mi][3],
                             bh[nj][0], bh[nj][1]);
                }
        }
    }
}

// ---------------------------------------------------------------------------
// Output projection: 2-product (Ah*Wh + Ah*Wl), fp32 C.
// ---------------------------------------------------------------------------
__global__ __launch_bounds__(256, 2)
void gemm_mma(const __half* __restrict__ Ah,
              const __half* __restrict__ Bh, const __half* __restrict__ Bl,
              float* __restrict__ C, int ldc)
{
    extern __shared__ char dsm[];
    const int tid = threadIdx.x;
    const int lane = tid & 31;
    const int m0 = blockIdx.y * 128;
    const int n0 = blockIdx.x * 128;

    GemmCtx cx;
    cx.sbase = smem_u32(dsm);
    gemm_lane_init(cx, tid);
    switch (tid >> 6) {
        case 0:  cx.gsrc = Ah; cx.row0 = m0; cx.smoff = 0;          break;
        case 1:  cx.gsrc = Bh; cx.row0 = n0; cx.smoff = TILE_B;     break;
        case 2:  cx.gsrc = Bl; cx.row0 = n0; cx.smoff = 2*TILE_B;   break;
        default: cx.gsrc = nullptr; cx.row0 = 0; cx.smoff = 0;      break;
    }

    float acc[4][4][4];
    #pragma unroll
    for (int i = 0; i < 4; i++)
        #pragma unroll
        for (int j = 0; j < 4; j++)
            #pragma unroll
            for (int q = 0; q < 4; q++) acc[i][j][q] = 0.0f;

    gemm_mainloop2(cx, acc);

    const int er = lane >> 2;
    const int ec = (lane & 3) * 2;
    #pragma unroll
    for (int mi = 0; mi < 4; mi++) {
        const int row_a = m0 + cx.m0w + mi * 16 + er;
        #pragma unroll
        for (int nj = 0; nj < 4; nj++) {
            const int col = n0 + cx.n0w + nj * 8 + ec;
            float* cc = acc[mi][nj];
            *reinterpret_cast<float2*>(C + (size_t)row_a * ldc + col) =
                make_float2(cc[0], cc[1]);
            *reinterpret_cast<float2*>(C + (size_t)(row_a + 8) * ldc + col) =
                make_float2(cc[2], cc[3]);
        }
    }
}

// ---------------------------------------------------------------------------
// QKV GEMM: 1-product (Ah*Wh), fused RoPE + scale + fp16 epilogue.
// ---------------------------------------------------------------------------
__global__ __launch_bounds__(256, 2)
void gemm_qkv_fused(const __half* __restrict__ Ah,
                    const __half* __restrict__ Bh,
                    __half* __restrict__ Qh,
                    __half* __restrict__ Kh,
                    __half* __restrict__ Vh)
{
    extern __shared__ char dsm[];
    const int tid = threadIdx.x;
    const int lane = tid & 31;
    const int m0 = blockIdx.y * 128;
    const int n0 = blockIdx.x * 128;

    GemmCtx cx;
    cx.sbase = smem_u32(dsm);
    gemm_lane_init(cx, tid);
    switch (tid >> 6) {
        case 0:  cx.gsrc = Ah; cx.row0 = m0; cx.smoff = 0;          break;
        case 1:  cx.gsrc = Bh; cx.row0 = n0; cx.smoff = TILE_B;     break;
        default: cx.gsrc = nullptr; cx.row0 = 0; cx.smoff = 0;      break;
    }

    float acc[4][4][4];
    #pragma unroll
    for (int i = 0; i < 4; i++)
        #pragma unroll
        for (int j = 0; j < 4; j++)
            #pragma unroll
            for (int q = 0; q < 4; q++) acc[i][j][q] = 0.0f;

    gemm_mainloop1(cx, acc);

    // ---- stage fp32 tile to smem [128][132] (67.6KB <= 68KB) ----
    __syncthreads();
    float* ft = reinterpret_cast<float*>(dsm);
    const int er = lane >> 2;
    const int ec = (lane & 3) * 2;
    #pragma unroll
    for (int mi = 0; mi < 4; mi++) {
        const int r = cx.m0w + mi * 16 + er;
        #pragma unroll
        for (int nj = 0; nj < 4; nj++) {
            const int c = cx.n0w + nj * 8 + ec;
            float* cc = acc[mi][nj];
            *reinterpret_cast<float2*>(ft + r * 132 + c)       = make_float2(cc[0], cc[1]);
            *reinterpret_cast<float2*>(ft + (r + 8) * 132 + c) = make_float2(cc[2], cc[3]);
        }
    }
    __syncthreads();

    // ---- fused epilogue by region ----
    if (n0 < QCOLS) {
        const int head = n0 >> 7;
        const float scale = 0.08838834764831845f;
        for (int it = 0; it < 32; it++) {
            const int idx = tid + it * 256;
            const int r = idx >> 6, i = idx & 63;
            const int grow = m0 + r;
            const int pos = grow & (SEQ - 1);
            const float x1 = ft[r * 132 + i];
            const float x2 = ft[r * 132 + i + 64];
            const float c = g_cos[pos * 64 + i];
            const float s = g_sin[pos * 64 + i];
            const float y1 = (x1 * c - x2 * s) * scale;
            const float y2 = (x2 * c + x1 * s) * scale;
            const size_t o = (size_t)grow * QCOLS + head * HDIM + i;
            Qh[o]      = __float2half_rn(y1);
            Qh[o + 64] = __float2half_rn(y2);
        }
    } else if (n0 < QCOLS + KCOLS) {
        const int head = (n0 - QCOLS) >> 7;
        for (int it = 0; it < 32; it++) {
            const int idx = tid + it * 256;
            const int r = idx >> 6, i = idx & 63;
            const int grow = m0 + r;
            const int pos = grow & (SEQ - 1);
            const float x1 = ft[r * 132 + i];
            const float x2 = ft[r * 132 + i + 64];
            const float c = g_cos[pos * 64 + i];
            const float s = g_sin[pos * 64 + i];
            const float y1 = x1 * c - x2 * s;
            const float y2 = x2 * c + x1 * s;
            const size_t o = (size_t)grow * KCOLS + head * HDIM + i;
            Kh[o]      = __float2half_rn(y1);
            Kh[o + 64] = __float2half_rn(y2);
        }
    } else {
        const int cbase = n0 - (QCOLS + KCOLS);
        for (int it = 0; it < 64; it++) {
            const int idx = tid + it * 256;
            const int r = idx >> 7, c = idx & 127;
            const int grow = m0 + r;
            const float x = ft[r * 132 + c];
            Vh[(size_t)grow * KCOLS + cbase + c] = __float2half_rn(x);
        }
    }
}

// ---------------------------------------------------------------------------
// Flash attention: pure fp16 single-product (Qh*Kh; Ph*Vh).
// FKT=64, 2-stage KV double buffer (Kh+Vh = 32KB/stage).
// Smem = 32 + 2*32 = 96KB -> 2 CTAs/SM. qt descending. Writes ctx hi only.
// ---------------------------------------------------------------------------
#define FQT 128
#define FKT 64
#define FQ_B    32768
#define FTILE_B 16384
#define FKV_B   (2*FTILE_B)                 // Kh,Vh per stage = 32KB
#define FLASH_SMEM (FQ_B + 2*FKV_B)         // 96KB

__global__ __launch_bounds__(256, 2)
void flash_mma(const __half* __restrict__ Qh_g,
               const __half* __restrict__ Kh_g,
               const __half* __restrict__ Vh_g,
               __half* __restrict__ Ch_g)
{
    extern __shared__ char dsm[];
    const uint32_t sb = smem_u32(dsm);
    const uint32_t Qh_s = sb;
    const uint32_t KV_s = sb + FQ_B;

    const int tid = threadIdx.x;
    const int w = tid >> 5, lane = tid & 31;
    const int qt = gridDim.x - 1 - blockIdx.x;
    const int h = blockIdx.y, b = blockIdx.z;
    const int kvh = h >> 2;
    const int qrow0 = b * SEQ + qt * FQT;
    const int nkt = 2 * qt + 2;

    {
        const int c = tid & 15, r0 = tid >> 4;
        #pragma unroll
        for (int i = 0; i < 8; i++) {
            const int r = r0 + i * 16;
            const size_t go = (size_t)(qrow0 + r) * QCOLS + h * HDIM + c * 8;
            cp_async16(Qh_s + SW(r, c), Qh_g + go);
        }
    }

    auto load_kv = [&](int kt, int st) {
        const int c = tid & 15, r0 = tid >> 4;
        const uint32_t base = KV_s + st * FKV_B;
        const int krow0 = b * SEQ + kt * FKT;
        #pragma unroll
        for (int i = 0; i < 4; i++) {
            const int r = r0 + i * 16;
            const size_t go = (size_t)(krow0 + r) * KCOLS + kvh * HDIM + c * 8;
            cp_async16(base +           SW(r, c), Kh_g + go);
            cp_async16(base + FTILE_B + SW(r, c), Vh_g + go);
        }
        asm volatile("cp.async.commit_group;\n" ::: "memory");
    };

    load_kv(0, 0);
    asm volatile("cp.async.commit_group;\n" ::: "memory");  // empty group (Q rides group 0)

    const int er = lane >> 2, ec = lane & 3;
    const int a_row = w * 16 + (lane & 15);
    const int a_kh  = lane >> 4;
    const int b_n   = (lane & 7) + ((lane >> 4) & 1) * 8;
    const int b_kh  = (lane >> 3) & 1;
    const int v_key = (lane & 7) + ((lane >> 3) & 1) * 8;
    const int v_dc  = lane >> 4;

    const int rg0 = qt * FQT + w * 16 + er;
    const int rg1 = rg0 + 8;

    float o[16][4];
    #pragma unroll
    for (int j = 0; j < 16; j++)
        #pragma unroll
        for (int q = 0; q < 4; q++) o[j][q] = 0.0f;
    float m0 = -1e30f, m1 = -1e30f, l0 = 0.0f, l1 = 0.0f;

    for (int kt = 0; kt < nkt; kt++) {
        const int st = kt & 1;
        if (kt + 1 < nkt) {
            load_kv(kt + 1, (kt + 1) & 1);
            asm volatile("cp.async.wait_group 1;\n" ::: "memory");
        } else {
            asm volatile("cp.async.wait_group 0;\n" ::: "memory");
        }
        __syncthreads();

        const uint32_t Kh_s = KV_s + st * FKV_B;
        const uint32_t Vh_s = Kh_s + FTILE_B;

        float s[8][4];
        #pragma unroll
        for (int f = 0; f < 8; f++)
            #pragma unroll
            for (int q = 0; q < 4; q++) s[f][q] = 0.0f;

        #pragma unroll
        for (int ks = 0; ks < 8; ks++) {
            uint32_t qa[4];
            ldsm_x4(qa[0], qa[1], qa[2], qa[3], Qh_s + SW(a_row, ks*2 + a_kh));
            #pragma unroll
            for (int ng = 0; ng < 4; ng++) {
                uint32_t kh0, kh1, kh2, kh3;
                ldsm_x4(kh0, kh1, kh2, kh3, Kh_s + SW(ng*16 + b_n, ks*2 + b_kh));
                float* s0 = s[ng*2];
                float* s1 = s[ng*2 + 1];
                mma16816(s0[0], s0[1], s0[2], s0[3], qa[0], qa[1], qa[2], qa[3], kh0, kh1);
                mma16816(s1[0], s1[1], s1[2], s1[3], qa[0], qa[1], qa[2], qa[3], kh2, kh3);
            }
        }

        if (kt >= 2 * qt) {
            #pragma unroll
            for (int f = 0; f < 8; f++) {
                const int key0 = kt * FKT + f * 8 + ec * 2;
                if (key0     > rg0) s[f][0] = -1e30f;
                if (key0 + 1 > rg0) s[f][1] = -1e30f;
                if (key0     > rg1) s[f][2] = -1e30f;
                if (key0 + 1 > rg1) s[f][3] = -1e30f;
            }
        }

        float nm0 = -1e30f, nm1 = -1e30f;
        #pragma unroll
        for (int f = 0; f < 8; f++) {
            nm0 = fmaxf(nm0, fmaxf(s[f][0], s[f][1]));
            nm1 = fmaxf(nm1, fmaxf(s[f][2], s[f][3]));
        }
        nm0 = fmaxf(nm0, __shfl_xor_sync(0xffffffffu, nm0, 1));
        nm0 = fmaxf(nm0, __shfl_xor_sync(0xffffffffu, nm0, 2));
        nm1 = fmaxf(nm1, __shfl_xor_sync(0xffffffffu, nm1, 1));
        nm1 = fmaxf(nm1, __shfl_xor_sync(0xffffffffu, nm1, 2));
        nm0 = fmaxf(nm0, m0);
        nm1 = fmaxf(nm1, m1);
        const float corr0 = __expf(m0 - nm0);
        const float corr1 = __expf(m1 - nm1);
        m0 = nm0;
        m1 = nm1;

        float rs0 = 0.0f, rs1 = 0.0f;
        #pragma unroll
        for (int f = 0; f < 8; f++) {
            s[f][0] = __expf(s[f][0] - nm0);
            s[f][1] = __expf(s[f][1] - nm0);
            s[f][2] = __expf(s[f][2] - nm1);
            s[f][3] = __expf(s[f][3] - nm1);
            rs0 += s[f][0] + s[f][1];
            rs1 += s[f][2] + s[f][3];
        }
        rs0 += __shfl_xor_sync(0xffffffffu, rs0, 1);
        rs0 += __shfl_xor_sync(0xffffffffu, rs0, 2);
        rs1 += __shfl_xor_sync(0xffffffffu, rs1, 1);
        rs1 += __shfl_xor_sync(0xffffffffu, rs1, 2);
        l0 = l0 * corr0 + rs0;
        l1 = l1 * corr1 + rs1;
        #pragma unroll
        for (int j = 0; j < 16; j++) {
            o[j][0] *= corr0; o[j][1] *= corr0;
            o[j][2] *= corr1; o[j][3] *= corr1;
        }

        #pragma unroll
        for (int kp = 0; kp < 4; kp++) {
            const float* f0 = s[2*kp];
            const float* f1 = s[2*kp + 1];
            uint32_t pa[4];
            __half2 t;
            t = __floats2half2_rn(f0[0], f0[1]); pa[0] = *reinterpret_cast<uint32_t*>(&t);
            t = __floats2half2_rn(f0[2], f0[3]); pa[1] = *reinterpret_cast<uint32_t*>(&t);
            t = __floats2half2_rn(f1[0], f1[1]); pa[2] = *reinterpret_cast<uint32_t*>(&t);
            t = __floats2half2_rn(f1[2], f1[3]); pa[3] = *reinterpret_cast<uint32_t*>(&t);

            #pragma unroll
            for (int nd = 0; nd < 8; nd++) {
                uint32_t vh0, vh1, vh2, vh3;
                ldsm_x4t(vh0, vh1, vh2, vh3, Vh_s + SW(kp*16 + v_key, nd*2 + v_dc));
                float* o0 = o[nd*2];
                float* o1 = o[nd*2 + 1];
                mma16816(o0[0], o0[1], o0[2], o0[3], pa[0], pa[1], pa[2], pa[3], vh0, vh1);
                mma16816(o1[0], o1[1], o1[2], o1[3], pa[0], pa[1], pa[2], pa[3], vh2, vh3);
            }
        }
        __syncthreads();   // all reads of stage st done
    }

    const float inv0 = 1.0f / l0;
    const float inv1 = 1.0f / l1;
    const size_t row0 = (size_t)(qrow0 + w * 16 + er);
    const size_t row1 = row0 + 8;
    #pragma unroll
    for (int j = 0; j < 16; j++) {
        const int col = h * HDIM + j * 8 + ec * 2;
        *reinterpret_cast<__half2*>(Ch_g + row0 * QCOLS + col) =
            __floats2half2_rn(o[j][0] * inv0, o[j][1] * inv0);
        *reinterpret_cast<__half2*>(Ch_g + row1 * QCOLS + col) =
            __floats2half2_rn(o[j][2] * inv1, o[j][3] * inv1);
    }
}

// ---------------------------------------------------------------------------
extern "C" void kernel_launch(void* const* d_in, const int* in_sizes, int n_in,
                              void* d_out, int out_size)
{
    const float* hidden = (const float*)d_in[0];
    const float* Wq = (const float*)d_in[1];
    const float* Wk = (const float*)d_in[2];
    const float* Wv = (const float*)d_in[3];
    const float* Wo = (const float*)d_in[4];
    float* out = (float*)d_out;

    __half *ah, *ch, *qh, *kh, *vh, *wh, *woh, *wol;
    cudaGetSymbolAddress((void**)&ah, g_ah);
    cudaGetSymbolAddress((void**)&ch, g_ch);
    cudaGetSymbolAddress((void**)&qh, g_qh);
    cudaGetSymbolAddress((void**)&kh, g_kh);
    cudaGetSymbolAddress((void**)&vh, g_vh);
    cudaGetSymbolAddress((void**)&wh, g_wh);
    cudaGetSymbolAddress((void**)&woh, g_woh); cudaGetSymbolAddress((void**)&wol, g_wol);

    cudaFuncSetAttribute(gemm_mma,
                         cudaFuncAttributeMaxDynamicSharedMemorySize, GEMM2_SMEM);
    cudaFuncSetAttribute(gemm_qkv_fused,
                         cudaFuncAttributeMaxDynamicSharedMemorySize, GEMM1_SMEM);
    cudaFuncSetAttribute(flash_mma,
                         cudaFuncAttributeMaxDynamicSharedMemorySize, FLASH_SMEM);

    // 1) RoPE table, 2) hidden hi-split, 3) all weight transposes (one launch)
    rope_table_kernel<<<(SEQ*64 + 255)/256, 256>>>();
    split_hi_kernel<<<(ROWS*HID/4 + 255)/256, 256>>>(hidden, ah, ROWS*HID/4);
    tsplit_all_kernel<<<10240, dim3(32,8)>>>(Wq, Wk, Wv, Wo, wh, woh, wol);

    // 4) Merged QKV projection (1-product) with fused RoPE/scale epilogue
    gemm_qkv_fused<<<dim3(QKVC/128, ROWS/128), 256, GEMM1_SMEM>>>(
        ah, wh, qh, kh, vh);

    // 5) Attention (pure fp16), writes ctx hi directly
    flash_mma<<<dim3(SEQ/FQT, NHQ, BATCH), 256, FLASH_SMEM>>>(qh, kh, vh, ch);

    // 6) Output projection (2-product — lo term lands on graded output)
    gemm_mma<<<dim3(HID/128, ROWS/128), 256, GEMM2_SMEM>>>(ch, woh, wol, out, HID);
}

// round 17
// speedup vs baseline: 1.6963x; 1.1698x over previous
#include <cuda_runtime.h>
#include <cuda_fp16.h>
#include <math.h>
#include <stdint.h>

// Problem constants
#define BATCH 2
#define SEQ   2048
#define HID   2048
#define NHQ   16
#define NKV   4
#define HDIM  128
#define ROWS  (BATCH*SEQ)          // 4096
#define QCOLS (NHQ*HDIM)           // 2048
#define KCOLS (NKV*HDIM)           // 512
#define QKVC  (QCOLS + 2*KCOLS)    // 3072

// ---------------------------------------------------------------------------
// Device scratch (static — no allocation allowed). All operands fp16 hi.
// ---------------------------------------------------------------------------
__device__ float g_cos[SEQ*64];
__device__ float g_sin[SEQ*64];

__device__ __half g_ah[ROWS*HID];                       // hidden
__device__ __half g_ch[ROWS*QCOLS];                     // ctx
__device__ __half g_qh[ROWS*QCOLS];                     // q (rope+scale)
__device__ __half g_kh[ROWS*KCOLS];                     // k (rope)
__device__ __half g_vh[ROWS*KCOLS];                     // v
__device__ __half g_wh[QKVC*HID];                       // [Wq;Wk;Wv]^T
__device__ __half g_woh[HID*QCOLS];                     // Wo^T

// ---------------------------------------------------------------------------
// Helpers
// ---------------------------------------------------------------------------
__device__ __forceinline__ uint32_t smem_u32(const void* p) {
    uint32_t a;
    asm("{ .reg .u64 t; cvta.to.shared.u64 t, %1; cvt.u32.u64 %0, t; }" : "=r"(a) : "l"(p));
    return a;
}
__device__ __forceinline__ void cp_async16(uint32_t dst, const void* src) {
    asm volatile("cp.async.cg.shared.global [%0], [%1], 16;\n" :: "r"(dst), "l"(src) : "memory");
}
__device__ __forceinline__ void ldsm_x4(uint32_t& r0, uint32_t& r1, uint32_t& r2, uint32_t& r3,
                                        uint32_t addr) {
    asm volatile("ldmatrix.sync.aligned.m8n8.x4.shared.b16 {%0,%1,%2,%3}, [%4];"
                 : "=r"(r0), "=r"(r1), "=r"(r2), "=r"(r3) : "r"(addr));
}
__device__ __forceinline__ void ldsm_x4t(uint32_t& r0, uint32_t& r1, uint32_t& r2, uint32_t& r3,
                                         uint32_t addr) {
    asm volatile("ldmatrix.sync.aligned.m8n8.x4.trans.shared.b16 {%0,%1,%2,%3}, [%4];"
                 : "=r"(r0), "=r"(r1), "=r"(r2), "=r"(r3) : "r"(addr));
}
__device__ __forceinline__ void mma16816(float& c0, float& c1, float& c2, float& c3,
                                         uint32_t a0, uint32_t a1, uint32_t a2, uint32_t a3,
                                         uint32_t b0, uint32_t b1) {
    asm volatile(
        "mma.sync.aligned.m16n8k16.row.col.f32.f16.f16.f32 "
        "{%0,%1,%2,%3}, {%4,%5,%6,%7}, {%8,%9}, {%0,%1,%2,%3};"
        : "+f"(c0), "+f"(c1), "+f"(c2), "+f"(c3)
        : "r"(a0), "r"(a1), "r"(a2), "r"(a3), "r"(b0), "r"(b1));
}
// flash smem swizzle: row r (256B rows of fp16[128]), 16B chunk c (0..15)
#define SW(r, c) ((uint32_t)((r) * 256 + (((c) ^ ((r) & 7)) << 4)))
// gemm smem swizzle: row r (128B rows of fp16[64]), 16B chunk c (0..7)
#define SWG(r, c) ((uint32_t)((r) * 128 + (((c) ^ ((r) & 7)) << 4)))

// ---------------------------------------------------------------------------
// fp32 -> fp16 hi (row-major, same layout)
// ---------------------------------------------------------------------------
__global__ void split_hi_kernel(const float* __restrict__ in,
                                __half* __restrict__ hi, int n4)
{
    int i = blockIdx.x * blockDim.x + threadIdx.x;
    if (i >= n4) return;
    float4 v = reinterpret_cast<const float4*>(in)[i];
    __half2* hp = reinterpret_cast<__half2*>(hi);
    hp[2*i]   = __floats2half2_rn(v.x, v.y);
    hp[2*i+1] = __floats2half2_rn(v.z, v.w);
}

// All weight transposes (fp16 hi only) in ONE launch.
__global__ void tsplit_all_kernel(const float* __restrict__ Wq, const float* __restrict__ Wk,
                                  const float* __restrict__ Wv, const float* __restrict__ Wo,
                                  __half* __restrict__ wh, __half* __restrict__ woh)
{
    __shared__ float t[32][33];
    const int bid = blockIdx.x;
    const float* src;
    __half *dh;
    int Nin, nbx, tile;
    if (bid < 4096)      { src = Wq; dh = wh; Nin = 2048; nbx = 64; tile = bid; }
    else if (bid < 5120) { src = Wk; dh = wh + (size_t)QCOLS*HID;
                           Nin = 512; nbx = 16; tile = bid - 4096; }
    else if (bid < 6144) { src = Wv; dh = wh + (size_t)(QCOLS+KCOLS)*HID;
                           Nin = 512; nbx = 16; tile = bid - 5120; }
    else                 { src = Wo; dh = woh; Nin = 2048; nbx = 64; tile = bid - 6144; }

    const int tx = threadIdx.x, ty = threadIdx.y;
    const int n0 = (tile % nbx) * 32, k0 = (tile / nbx) * 32;
    #pragma unroll
    for (int j = 0; j < 32; j += 8)
        t[ty + j][tx] = src[(size_t)(k0 + ty + j) * Nin + n0 + tx];
    __syncthreads();
    #pragma unroll
    for (int j = 0; j < 32; j += 8) {
        float x = t[tx][ty + j];
        dh[(size_t)(n0 + ty + j) * 2048 + k0 + tx] = __float2half_rn(x);
    }
}

// ---------------------------------------------------------------------------
// RoPE table
// ---------------------------------------------------------------------------
__global__ void rope_table_kernel()
{
    int idx = blockIdx.x * blockDim.x + threadIdx.x;
    if (idx >= SEQ * 64) return;
    int pos = idx >> 6, i = idx & 63;
    double inv = exp2(-(double)i * (13.287712379549449 / 64.0));
    double ang = (double)pos * inv;
    const double twopi = 6.283185307179586476925286766559;
    ang -= floor(ang * (1.0 / twopi)) * twopi;
    if (ang > 3.14159265358979323846) ang -= twopi;
    float s, c;
    sincosf((float)ang, &s, &c);
    g_cos[idx] = c;
    g_sin[idx] = s;
}

// ---------------------------------------------------------------------------
// GEMM: 128x128 CTA tile, fp16 single-product (Ah*Bh).
// KCH=64 (32 chunks), 2-stage double buffer, one sync per chunk, 2 CTAs/SM.
// Stage = Ah+Bh = 32KB; 2 stages = 64KB.
// ---------------------------------------------------------------------------
#define KCH       64
#define NCHUNKS   32
#define TILE_B    16384           // 128 rows x 128 B
#define STAGE1_B  (2*TILE_B)      // 32 KB
#define GEMMO_SMEM (2*STAGE1_B)   // 64 KB (out-proj, fp32 epilogue from regs)
#define GEMM1_SMEM 69632          // 68 KB (QKV: covers fp32 epilogue tile)

struct GemmCtx {
    uint32_t sbase;
    const __half* gsrc;
    int row0, lch, lr0;
    uint32_t smoff;
    int m0w, n0w;
    int a_row, a_kh, b_row, b_kh;
};

__device__ __forceinline__ void gemm_lane_init(GemmCtx& cx, int tid)
{
    const int wid = tid >> 5, lane = tid & 31;
    cx.m0w = (wid & 1) * 64;
    cx.n0w = (wid >> 1) * 32;
    cx.a_row = lane & 15;
    cx.a_kh  = lane >> 4;
    cx.b_row = (lane & 7) + ((lane >> 4) & 1) * 8;
    cx.b_kh  = (lane >> 3) & 1;
    const int t6 = tid & 63;
    cx.lch = t6 & 7;
    cx.lr0 = t6 >> 3;
}

__device__ __forceinline__ void gemm_mainloop1(
    const GemmCtx& cx, float acc[4][4][4])
{
    auto load_chunk = [&](int ci, int st) {
        if (cx.gsrc) {
            const uint32_t tb = cx.sbase + st * STAGE1_B + cx.smoff;
            #pragma unroll
            for (int i = 0; i < 16; i++) {
                const int r = cx.lr0 + i * 8;
                cp_async16(tb + SWG(r, cx.lch),
                           cx.gsrc + (size_t)(cx.row0 + r) * 2048 + ci * KCH + cx.lch * 8);
            }
        }
        asm volatile("cp.async.commit_group;\n" ::: "memory");
    };

    load_chunk(0, 0);

    for (int ci = 0; ci < NCHUNKS; ci++) {
        asm volatile("cp.async.wait_group 0;\n" ::: "memory");
        __syncthreads();
        if (ci + 1 < NCHUNKS) load_chunk(ci + 1, (ci + 1) & 1);

        const uint32_t ah_b = cx.sbase + (ci & 1) * STAGE1_B;
        const uint32_t bh_b = ah_b + TILE_B;

        #pragma unroll
        for (int ks = 0; ks < 4; ks++) {
            uint32_t a4[4][4];
            #pragma unroll
            for (int mi = 0; mi < 4; mi++) {
                const int r = cx.m0w + mi * 16 + cx.a_row;
                ldsm_x4(a4[mi][0], a4[mi][1], a4[mi][2], a4[mi][3],
                        ah_b + SWG(r, ks * 2 + cx.a_kh));
            }
            uint32_t bh[4][2];
            #pragma unroll
            for (int jb = 0; jb < 2; jb++) {
                const int r = cx.n0w + jb * 16 + cx.b_row;
                const uint32_t off = SWG(r, ks * 2 + cx.b_kh);
                ldsm_x4(bh[2*jb][0], bh[2*jb][1], bh[2*jb+1][0], bh[2*jb+1][1], bh_b + off);
            }
            #pragma unroll
            for (int mi = 0; mi < 4; mi++)
                #pragma unroll
                for (int nj = 0; nj < 4; nj++) {
                    float* cc = acc[mi][nj];
                    mma16816(cc[0], cc[1], cc[2], cc[3],
                             a4[mi][0], a4[mi][1], a4[mi][2], a4[mi][3],
                             bh[nj][0], bh[nj][1]);
                }
        }
    }
}

__device__ __forceinline__ void gemm_src_init(
    GemmCtx& cx, int tid, int m0, int n0,
    const __half* Ah, const __half* Bh)
{
    switch (tid >> 6) {
        case 0:  cx.gsrc = Ah; cx.row0 = m0; cx.smoff = 0;      break;
        case 1:  cx.gsrc = Bh; cx.row0 = n0; cx.smoff = TILE_B; break;
        default: cx.gsrc = nullptr; cx.row0 = 0; cx.smoff = 0;  break;
    }
}

// ---------------------------------------------------------------------------
// Output projection: 1-product (Ah*Wh), fp32 C.
// ---------------------------------------------------------------------------
__global__ __launch_bounds__(256, 2)
void gemm_mma(const __half* __restrict__ Ah,
              const __half* __restrict__ Bh,
              float* __restrict__ C, int ldc)
{
    extern __shared__ char dsm[];
    const int tid = threadIdx.x;
    const int lane = tid & 31;
    const int m0 = blockIdx.y * 128;
    const int n0 = blockIdx.x * 128;

    GemmCtx cx;
    cx.sbase = smem_u32(dsm);
    gemm_lane_init(cx, tid);
    gemm_src_init(cx, tid, m0, n0, Ah, Bh);

    float acc[4][4][4];
    #pragma unroll
    for (int i = 0; i < 4; i++)
        #pragma unroll
        for (int j = 0; j < 4; j++)
            #pragma unroll
            for (int q = 0; q < 4; q++) acc[i][j][q] = 0.0f;

    gemm_mainloop1(cx, acc);

    const int er = lane >> 2;
    const int ec = (lane & 3) * 2;
    #pragma unroll
    for (int mi = 0; mi < 4; mi++) {
        const int row_a = m0 + cx.m0w + mi * 16 + er;
        #pragma unroll
        for (int nj = 0; nj < 4; nj++) {
            const int col = n0 + cx.n0w + nj * 8 + ec;
            float* cc = acc[mi][nj];
            *reinterpret_cast<float2*>(C + (size_t)row_a * ldc + col) =
                make_float2(cc[0], cc[1]);
            *reinterpret_cast<float2*>(C + (size_t)(row_a + 8) * ldc + col) =
                make_float2(cc[2], cc[3]);
        }
    }
}

// ---------------------------------------------------------------------------
// QKV GEMM: 1-product, fused RoPE + scale + fp16 epilogue.
// ---------------------------------------------------------------------------
__global__ __launch_bounds__(256, 2)
void gemm_qkv_fused(const __half* __restrict__ Ah,
                    const __half* __restrict__ Bh,
                    __half* __restrict__ Qh,
                    __half* __restrict__ Kh,
                    __half* __restrict__ Vh)
{
    extern __shared__ char dsm[];
    const int tid = threadIdx.x;
    const int lane = tid & 31;
    const int m0 = blockIdx.y * 128;
    const int n0 = blockIdx.x * 128;

    GemmCtx cx;
    cx.sbase = smem_u32(dsm);
    gemm_lane_init(cx, tid);
    gemm_src_init(cx, tid, m0, n0, Ah, Bh);

    float acc[4][4][4];
    #pragma unroll
    for (int i = 0; i < 4; i++)
        #pragma unroll
        for (int j = 0; j < 4; j++)
            #pragma unroll
            for (int q = 0; q < 4; q++) acc[i][j][q] = 0.0f;

    gemm_mainloop1(cx, acc);

    // ---- stage fp32 tile to smem [128][132] (67.6KB <= 68KB) ----
    __syncthreads();
    float* ft = reinterpret_cast<float*>(dsm);
    const int er = lane >> 2;
    const int ec = (lane & 3) * 2;
    #pragma unroll
    for (int mi = 0; mi < 4; mi++) {
        const int r = cx.m0w + mi * 16 + er;
        #pragma unroll
        for (int nj = 0; nj < 4; nj++) {
            const int c = cx.n0w + nj * 8 + ec;
            float* cc = acc[mi][nj];
            *reinterpret_cast<float2*>(ft + r * 132 + c)       = make_float2(cc[0], cc[1]);
            *reinterpret_cast<float2*>(ft + (r + 8) * 132 + c) = make_float2(cc[2], cc[3]);
        }
    }
    __syncthreads();

    // ---- fused epilogue by region ----
    if (n0 < QCOLS) {
        const int head = n0 >> 7;
        const float scale = 0.08838834764831845f;
        for (int it = 0; it < 32; it++) {
            const int idx = tid + it * 256;
            const int r = idx >> 6, i = idx & 63;
            const int grow = m0 + r;
            const int pos = grow & (SEQ - 1);
            const float x1 = ft[r * 132 + i];
            const float x2 = ft[r * 132 + i + 64];
            const float c = g_cos[pos * 64 + i];
            const float s = g_sin[pos * 64 + i];
            const float y1 = (x1 * c - x2 * s) * scale;
            const float y2 = (x2 * c + x1 * s) * scale;
            const size_t o = (size_t)grow * QCOLS + head * HDIM + i;
            Qh[o]      = __float2half_rn(y1);
            Qh[o + 64] = __float2half_rn(y2);
        }
    } else if (n0 < QCOLS + KCOLS) {
        const int head = (n0 - QCOLS) >> 7;
        for (int it = 0; it < 32; it++) {
            const int idx = tid + it * 256;
            const int r = idx >> 6, i = idx & 63;
            const int grow = m0 + r;
            const int pos = grow & (SEQ - 1);
            const float x1 = ft[r * 132 + i];
            const float x2 = ft[r * 132 + i + 64];
            const float c = g_cos[pos * 64 + i];
            const float s = g_sin[pos * 64 + i];
            const float y1 = x1 * c - x2 * s;
            const float y2 = x2 * c + x1 * s;
            const size_t o = (size_t)grow * KCOLS + head * HDIM + i;
            Kh[o]      = __float2half_rn(y1);
            Kh[o + 64] = __float2half_rn(y2);
        }
    } else {
        const int cbase = n0 - (QCOLS + KCOLS);
        for (int it = 0; it < 64; it++) {
            const int idx = tid + it * 256;
            const int r = idx >> 7, c = idx & 127;
            const int grow = m0 + r;
            const float x = ft[r * 132 + c];
            Vh[(size_t)grow * KCOLS + cbase + c] = __float2half_rn(x);
        }
    }
}

// ---------------------------------------------------------------------------
// Flash attention: pure fp16 single-product (Qh*Kh; Ph*Vh).
// FKT=64, 2-stage KV double buffer (Kh+Vh = 32KB/stage).
// Smem = 32 + 2*32 = 96KB -> 2 CTAs/SM. qt descending. Writes ctx hi only.
// ---------------------------------------------------------------------------
#define FQT 128
#define FKT 64
#define FQ_B    32768
#define FTILE_B 16384
#define FKV_B   (2*FTILE_B)                 // Kh,Vh per stage = 32KB
#define FLASH_SMEM (FQ_B + 2*FKV_B)         // 96KB

__global__ __launch_bounds__(256, 2)
void flash_mma(const __half* __restrict__ Qh_g,
               const __half* __restrict__ Kh_g,
               const __half* __restrict__ Vh_g,
               __half* __restrict__ Ch_g)
{
    extern __shared__ char dsm[];
    const uint32_t sb = smem_u32(dsm);
    const uint32_t Qh_s = sb;
    const uint32_t KV_s = sb + FQ_B;

    const int tid = threadIdx.x;
    const int w = tid >> 5, lane = tid & 31;
    const int qt = gridDim.x - 1 - blockIdx.x;
    const int h = blockIdx.y, b = blockIdx.z;
    const int kvh = h >> 2;
    const int qrow0 = b * SEQ + qt * FQT;
    const int nkt = 2 * qt + 2;

    {
        const int c = tid & 15, r0 = tid >> 4;
        #pragma unroll
        for (int i = 0; i < 8; i++) {
            const int r = r0 + i * 16;
            const size_t go = (size_t)(qrow0 + r) * QCOLS + h * HDIM + c * 8;
            cp_async16(Qh_s + SW(r, c), Qh_g + go);
        }
    }

    auto load_kv = [&](int kt, int st) {
        const int c = tid & 15, r0 = tid >> 4;
        const uint32_t base = KV_s + st * FKV_B;
        const int krow0 = b * SEQ + kt * FKT;
        #pragma unroll
        for (int i = 0; i < 4; i++) {
            const int r = r0 + i * 16;
            const size_t go = (size_t)(krow0 + r) * KCOLS + kvh * HDIM + c * 8;
            cp_async16(base +           SW(r, c), Kh_g + go);
            cp_async16(base + FTILE_B + SW(r, c), Vh_g + go);
        }
        asm volatile("cp.async.commit_group;\n" ::: "memory");
    };

    load_kv(0, 0);
    asm volatile("cp.async.commit_group;\n" ::: "memory");  // empty group (Q rides group 0)

    const int er = lane >> 2, ec = lane & 3;
    const int a_row = w * 16 + (lane & 15);
    const int a_kh  = lane >> 4;
    const int b_n   = (lane & 7) + ((lane >> 4) & 1) * 8;
    const int b_kh  = (lane >> 3) & 1;
    const int v_key = (lane & 7) + ((lane >> 3) & 1) * 8;
    const int v_dc  = lane >> 4;

    const int rg0 = qt * FQT + w * 16 + er;
    const int rg1 = rg0 + 8;

    float o[16][4];
    #pragma unroll
    for (int j = 0; j < 16; j++)
        #pragma unroll
        for (int q = 0; q < 4; q++) o[j][q] = 0.0f;
    float m0 = -1e30f, m1 = -1e30f, l0 = 0.0f, l1 = 0.0f;

    for (int kt = 0; kt < nkt; kt++) {
        const int st = kt & 1;
        if (kt + 1 < nkt) {
            load_kv(kt + 1, (kt + 1) & 1);
            asm volatile("cp.async.wait_group 1;\n" ::: "memory");
        } else {
            asm volatile("cp.async.wait_group 0;\n" ::: "memory");
        }
        __syncthreads();

        const uint32_t Kh_s = KV_s + st * FKV_B;
        const uint32_t Vh_s = Kh_s + FTILE_B;

        float s[8][4];
        #pragma unroll
        for (int f = 0; f < 8; f++)
            #pragma unroll
            for (int q = 0; q < 4; q++) s[f][q] = 0.0f;

        #pragma unroll
        for (int ks = 0; ks < 8; ks++) {
            uint32_t qa[4];
            ldsm_x4(qa[0], qa[1], qa[2], qa[3], Qh_s + SW(a_row, ks*2 + a_kh));
            #pragma unroll
            for (int ng = 0; ng < 4; ng++) {
                uint32_t kh0, kh1, kh2, kh3;
                ldsm_x4(kh0, kh1, kh2, kh3, Kh_s + SW(ng*16 + b_n, ks*2 + b_kh));
                float* s0 = s[ng*2];
                float* s1 = s[ng*2 + 1];
                mma16816(s0[0], s0[1], s0[2], s0[3], qa[0], qa[1], qa[2], qa[3], kh0, kh1);
                mma16816(s1[0], s1[1], s1[2], s1[3], qa[0], qa[1], qa[2], qa[3], kh2, kh3);
            }
        }

        if (kt >= 2 * qt) {
            #pragma unroll
            for (int f = 0; f < 8; f++) {
                const int key0 = kt * FKT + f * 8 + ec * 2;
                if (key0     > rg0) s[f][0] = -1e30f;
                if (key0 + 1 > rg0) s[f][1] = -1e30f;
                if (key0     > rg1) s[f][2] = -1e30f;
                if (key0 + 1 > rg1) s[f][3] = -1e30f;
            }
        }

        float nm0 = -1e30f, nm1 = -1e30f;
        #pragma unroll
        for (int f = 0; f < 8; f++) {
            nm0 = fmaxf(nm0, fmaxf(s[f][0], s[f][1]));
            nm1 = fmaxf(nm1, fmaxf(s[f][2], s[f][3]));
        }
        nm0 = fmaxf(nm0, __shfl_xor_sync(0xffffffffu, nm0, 1));
        nm0 = fmaxf(nm0, __shfl_xor_sync(0xffffffffu, nm0, 2));
        nm1 = fmaxf(nm1, __shfl_xor_sync(0xffffffffu, nm1, 1));
        nm1 = fmaxf(nm1, __shfl_xor_sync(0xffffffffu, nm1, 2));
        nm0 = fmaxf(nm0, m0);
        nm1 = fmaxf(nm1, m1);
        const float corr0 = __expf(m0 - nm0);
        const float corr1 = __expf(m1 - nm1);
        m0 = nm0;
        m1 = nm1;

        float rs0 = 0.0f, rs1 = 0.0f;
        #pragma unroll
        for (int f = 0; f < 8; f++) {
            s[f][0] = __expf(s[f][0] - nm0);
            s[f][1] = __expf(s[f][1] - nm0);
            s[f][2] = __expf(s[f][2] - nm1);
            s[f][3] = __expf(s[f][3] - nm1);
            rs0 += s[f][0] + s[f][1];
            rs1 += s[f][2] + s[f][3];
        }
        rs0 += __shfl_xor_sync(0xffffffffu, rs0, 1);
        rs0 += __shfl_xor_sync(0xffffffffu, rs0, 2);
        rs1 += __shfl_xor_sync(0xffffffffu, rs1, 1);
        rs1 += __shfl_xor_sync(0xffffffffu, rs1, 2);
        l0 = l0 * corr0 + rs0;
        l1 = l1 * corr1 + rs1;
        #pragma unroll
        for (int j = 0; j < 16; j++) {
            o[j][0] *= corr0; o[j][1] *= corr0;
            o[j][2] *= corr1; o[j][3] *= corr1;
        }

        #pragma unroll
        for (int kp = 0; kp < 4; kp++) {
            const float* f0 = s[2*kp];
            const float* f1 = s[2*kp + 1];
            uint32_t pa[4];
            __half2 t;
            t = __floats2half2_rn(f0[0], f0[1]); pa[0] = *reinterpret_cast<uint32_t*>(&t);
            t = __floats2half2_rn(f0[2], f0[3]); pa[1] = *reinterpret_cast<uint32_t*>(&t);
            t = __floats2half2_rn(f1[0], f1[1]); pa[2] = *reinterpret_cast<uint32_t*>(&t);
            t = __floats2half2_rn(f1[2], f1[3]); pa[3] = *reinterpret_cast<uint32_t*>(&t);

            #pragma unroll
            for (int nd = 0; nd < 8; nd++) {
                uint32_t vh0, vh1, vh2, vh3;
                ldsm_x4t(vh0, vh1, vh2, vh3, Vh_s + SW(kp*16 + v_key, nd*2 + v_dc));
                float* o0 = o[nd*2];
                float* o1 = o[nd*2 + 1];
                mma16816(o0[0], o0[1], o0[2], o0[3], pa[0], pa[1], pa[2], pa[3], vh0, vh1);
                mma16816(o1[0], o1[1], o1[2], o1[3], pa[0], pa[1], pa[2], pa[3], vh2, vh3);
            }
        }
        __syncthreads();   // all reads of stage st done
    }

    const float inv0 = 1.0f / l0;
    const float inv1 = 1.0f / l1;
    const size_t row0 = (size_t)(qrow0 + w * 16 + er);
    const size_t row1 = row0 + 8;
    #pragma unroll
    for (int j = 0; j < 16; j++) {
        const int col = h * HDIM + j * 8 + ec * 2;
        *reinterpret_cast<__half2*>(Ch_g + row0 * QCOLS + col) =
            __floats2half2_rn(o[j][0] * inv0, o[j][1] * inv0);
        *reinterpret_cast<__half2*>(Ch_g + row1 * QCOLS + col) =
            __floats2half2_rn(o[j][2] * inv1, o[j][3] * inv1);
    }
}

// ---------------------------------------------------------------------------
extern "C" void kernel_launch(void* const* d_in, const int* in_sizes, int n_in,
                              void* d_out, int out_size)
{
    const float* hidden = (const float*)d_in[0];
    const float* Wq = (const float*)d_in[1];
    const float* Wk = (const float*)d_in[2];
    const float* Wv = (const float*)d_in[3];
    const float* Wo = (const float*)d_in[4];
    float* out = (float*)d_out;

    __half *ah, *ch, *qh, *kh, *vh, *wh, *woh;
    cudaGetSymbolAddress((void**)&ah, g_ah);
    cudaGetSymbolAddress((void**)&ch, g_ch);
    cudaGetSymbolAddress((void**)&qh, g_qh);
    cudaGetSymbolAddress((void**)&kh, g_kh);
    cudaGetSymbolAddress((void**)&vh, g_vh);
    cudaGetSymbolAddress((void**)&wh, g_wh);
    cudaGetSymbolAddress((void**)&woh, g_woh);

    cudaFuncSetAttribute(gemm_mma,
                         cudaFuncAttributeMaxDynamicSharedMemorySize, GEMMO_SMEM);
    cudaFuncSetAttribute(gemm_qkv_fused,
                         cudaFuncAttributeMaxDynamicSharedMemorySize, GEMM1_SMEM);
    cudaFuncSetAttribute(flash_mma,
                         cudaFuncAttributeMaxDynamicSharedMemorySize, FLASH_SMEM);

    // 1) RoPE table, 2) hidden hi-split, 3) all weight transposes (one launch)
    rope_table_kernel<<<(SEQ*64 + 255)/256, 256>>>();
    split_hi_kernel<<<(ROWS*HID/4 + 255)/256, 256>>>(hidden, ah, ROWS*HID/4);
    tsplit_all_kernel<<<10240, dim3(32,8)>>>(Wq, Wk, Wv, Wo, wh, woh);

    // 4) Merged QKV projection (1-product) with fused RoPE/scale epilogue
    gemm_qkv_fused<<<dim3(QKVC/128, ROWS/128), 256, GEMM1_SMEM>>>(
        ah, wh, qh, kh, vh);

    // 5) Attention (pure fp16), writes ctx hi directly
    flash_mma<<<dim3(SEQ/FQT, NHQ, BATCH), 256, FLASH_SMEM>>>(qh, kh, vh, ch);

    // 6) Output projection (1-product)
    gemm_mma<<<dim3(HID/128, ROWS/128), 256, GEMMO_SMEM>>>(ch, woh, out, HID);
}